// round 2
// baseline (speedup 1.0000x reference)
#include <cuda_runtime.h>
#include <math.h>

#define BB    32
#define TTEXT 400
#define TMEL  1600
#define ADIM  384
#define ODIM  80

// ---------------- static scratch (no allocations allowed) ----------------
__device__ float g_h1[(size_t)BB * TTEXT * ADIM];
__device__ float g_h2[(size_t)BB * TTEXT * ADIM];
__device__ float g_y1[(size_t)BB * TMEL * ADIM];
__device__ float g_y2[(size_t)BB * TMEL * ADIM];
__device__ float g_tw1t[3 * ADIM * ADIM];
__device__ float g_tw2t[1 * ADIM * ADIM];
__device__ float g_mw1t[3 * ODIM * ADIM];
__device__ float g_mw2t[3 * ADIM * ADIM];
__device__ float g_mw3t[1 * ADIM * ADIM];
__device__ float g_hn[BB * TTEXT];
__device__ float g_yn[BB * TMEL];

// ---------------- weight transpose: W[co][ci][k] -> Wt[k][ci][co] ----------------
__global__ void wtrans_k(const float* __restrict__ W, float* __restrict__ Wt,
                         int CIN, int K)
{
    int idx = blockIdx.x * 256 + threadIdx.x;
    int total = 384 * CIN * K;
    if (idx >= total) return;
    int k  = idx % K;
    int ci = (idx / K) % CIN;
    int co = idx / (K * CIN);
    Wt[((size_t)k * CIN + ci) * 384 + co] = W[idx];
}

// ---------------- conv1d as tiled GEMM over taps ----------------
// X: [B, T, CIN] (time-major), Wt: [K][CIN][384], Out: [B, T, 384]
// grid: (ceil(T/64), 6, B), block (16,16), 4x4 microtile per thread.
template<int CIN, int KS, bool RELU>
__global__ __launch_bounds__(256)
void conv1d_k(const float* __restrict__ X, const float* __restrict__ Wt,
              const float* __restrict__ bias, float* __restrict__ Out, int T)
{
    constexpr int PAD   = (KS - 1) / 2;
    constexpr int XROWS = 64 + KS - 1;
    __shared__ float Xs[XROWS][16];
    __shared__ float Ws[KS][16][64];

    const int b  = blockIdx.z;
    const int t0 = blockIdx.x * 64;
    const int n0 = blockIdx.y * 64;
    const int tx = threadIdx.x, ty = threadIdx.y;
    const int tid = ty * 16 + tx;
    const float* Xb = X + (size_t)b * T * CIN;

    float acc[4][4] = {};

    for (int kc = 0; kc < CIN; kc += 16) {
        // load X halo tile (zero-padded at edges)
        #pragma unroll
        for (int i = tid; i < XROWS * 16; i += 256) {
            int r = i >> 4, c = i & 15;
            int t = t0 + r - PAD;
            Xs[r][c] = (t >= 0 && t < T) ? Xb[(size_t)t * CIN + kc + c] : 0.f;
        }
        // load weight tile (coalesced in co)
        #pragma unroll
        for (int i = tid; i < KS * 16 * 64; i += 256) {
            int k   = i / (16 * 64);
            int rem = i - k * (16 * 64);
            int c = rem >> 6, n = rem & 63;
            Ws[k][c][n] = Wt[((size_t)k * CIN + kc + c) * 384 + n0 + n];
        }
        __syncthreads();

        #pragma unroll
        for (int kk = 0; kk < 16; kk++) {
            float xr[4 + KS - 1];
            #pragma unroll
            for (int r = 0; r < 4 + KS - 1; r++) xr[r] = Xs[ty * 4 + r][kk];
            #pragma unroll
            for (int k = 0; k < KS; k++) {
                float4 bv = *(const float4*)&Ws[k][kk][tx * 4];
                #pragma unroll
                for (int i = 0; i < 4; i++) {
                    acc[i][0] += xr[i + k] * bv.x;
                    acc[i][1] += xr[i + k] * bv.y;
                    acc[i][2] += xr[i + k] * bv.z;
                    acc[i][3] += xr[i + k] * bv.w;
                }
            }
        }
        __syncthreads();
    }

    float4 bb = *(const float4*)&bias[n0 + tx * 4];
    #pragma unroll
    for (int i = 0; i < 4; i++) {
        int t = t0 + ty * 4 + i;
        if (t < T) {
            float4 v;
            v.x = acc[i][0] + bb.x;
            v.y = acc[i][1] + bb.y;
            v.z = acc[i][2] + bb.z;
            v.w = acc[i][3] + bb.w;
            if (RELU) {
                v.x = fmaxf(v.x, 0.f); v.y = fmaxf(v.y, 0.f);
                v.z = fmaxf(v.z, 0.f); v.w = fmaxf(v.w, 0.f);
            }
            *(float4*)&Out[((size_t)b * T + t) * 384 + n0 + tx * 4] = v;
        }
    }
}

// ---------------- row squared-norms over 384 features ----------------
__global__ void rownorm_k(const float* __restrict__ X, float* __restrict__ Nrm)
{
    int row = blockIdx.x;
    const float* p = X + (size_t)row * 384;
    float s = 0.f;
    for (int i = threadIdx.x; i < 384; i += 128) { float v = p[i]; s += v * v; }
    #pragma unroll
    for (int o = 16; o > 0; o >>= 1) s += __shfl_xor_sync(0xffffffffu, s, o);
    __shared__ float ps[4];
    if ((threadIdx.x & 31) == 0) ps[threadIdx.x >> 5] = s;
    __syncthreads();
    if (threadIdx.x == 0) Nrm[row] = ps[0] + ps[1] + ps[2] + ps[3];
}

// ---------------- fused distance GEMM + sqrt + mask + log_softmax ----------------
// Y: [B,1600,384], H: [B,400,384]. Out: [B,1600,400].
// grid: (1600/64, B), block (16,16). Each thread: 4 mel rows x 25 text cols.
__global__ __launch_bounds__(256)
void attn_k(const float* __restrict__ Y, const float* __restrict__ H,
            const float* __restrict__ Yn, const float* __restrict__ Hn,
            const unsigned char* __restrict__ mask, float* __restrict__ Out)
{
    const int b  = blockIdx.y;
    const int m0 = blockIdx.x * 64;
    const int tx = threadIdx.x, ty = threadIdx.y;
    const int tid = ty * 16 + tx;

    __shared__ float Hs[400][17];
    __shared__ float Ysm[64][17];
    __shared__ float sHn[400];
    __shared__ unsigned char sM[400];

    const float* Hb = H + (size_t)b * TTEXT * ADIM;
    const float* Yb = Y + ((size_t)b * TMEL + m0) * ADIM;

    for (int i = tid; i < 400; i += 256) {
        sHn[i] = Hn[b * TTEXT + i];
        sM[i]  = mask[b * TTEXT + i];
    }

    float s[4][25] = {};

    for (int kc = 0; kc < ADIM; kc += 16) {
        for (int i = tid; i < 400 * 16; i += 256) {
            int r = i >> 4, c = i & 15;
            Hs[r][c] = Hb[(size_t)r * ADIM + kc + c];
        }
        #pragma unroll
        for (int i = tid; i < 64 * 16; i += 256) {
            int r = i >> 4, c = i & 15;
            Ysm[r][c] = Yb[(size_t)r * ADIM + kc + c];
        }
        __syncthreads();

        #pragma unroll
        for (int kk = 0; kk < 16; kk++) {
            float yv[4];
            #pragma unroll
            for (int r = 0; r < 4; r++) yv[r] = Ysm[ty * 4 + r][kk];
            #pragma unroll
            for (int j = 0; j < 25; j++) {
                float hv = Hs[tx + 16 * j][kk];
                #pragma unroll
                for (int r = 0; r < 4; r++) s[r][j] += yv[r] * hv;
            }
        }
        __syncthreads();
    }

    // epilogue: score = -sqrt(max(||y||^2 + ||h||^2 - 2*dot, 1e-12)), then log_softmax
    #pragma unroll
    for (int r = 0; r < 4; r++) {
        int m = m0 + ty * 4 + r;
        float yn = Yn[b * TMEL + m];
        float mx = -INFINITY;
        #pragma unroll
        for (int j = 0; j < 25; j++) {
            int t = tx + 16 * j;
            float sq = yn + sHn[t] - 2.f * s[r][j];
            float d  = sqrtf(fmaxf(sq, 1e-12f));
            float sc = sM[t] ? -INFINITY : -d;
            s[r][j] = sc;
            mx = fmaxf(mx, sc);
        }
        #pragma unroll
        for (int o = 8; o > 0; o >>= 1)
            mx = fmaxf(mx, __shfl_xor_sync(0xffffffffu, mx, o, 16));
        float sum = 0.f;
        #pragma unroll
        for (int j = 0; j < 25; j++) sum += __expf(s[r][j] - mx);
        #pragma unroll
        for (int o = 8; o > 0; o >>= 1)
            sum += __shfl_xor_sync(0xffffffffu, sum, o, 16);
        float lse = mx + __logf(sum);
        float* op = Out + ((size_t)b * TMEL + m) * TTEXT;
        #pragma unroll
        for (int j = 0; j < 25; j++) op[tx + 16 * j] = s[r][j] - lse;
    }
}

// ---------------- launch ----------------
extern "C" void kernel_launch(void* const* d_in, const int* in_sizes, int n_in,
                              void* d_out, int out_size)
{
    const float* hs   = (const float*)d_in[0];
    const float* ys   = (const float*)d_in[1];
    const unsigned char* mask = (const unsigned char*)d_in[2];
    const float* t_w1 = (const float*)d_in[3];
    const float* t_b1 = (const float*)d_in[4];
    const float* t_w2 = (const float*)d_in[5];
    const float* t_b2 = (const float*)d_in[6];
    const float* m_w1 = (const float*)d_in[7];
    const float* m_b1 = (const float*)d_in[8];
    const float* m_w2 = (const float*)d_in[9];
    const float* m_b2 = (const float*)d_in[10];
    const float* m_w3 = (const float*)d_in[11];
    const float* m_b3 = (const float*)d_in[12];
    float* out = (float*)d_out;

    float *h1, *h2, *y1, *y2, *tw1t, *tw2t, *mw1t, *mw2t, *mw3t, *hn, *yn;
    cudaGetSymbolAddress((void**)&h1,   g_h1);
    cudaGetSymbolAddress((void**)&h2,   g_h2);
    cudaGetSymbolAddress((void**)&y1,   g_y1);
    cudaGetSymbolAddress((void**)&y2,   g_y2);
    cudaGetSymbolAddress((void**)&tw1t, g_tw1t);
    cudaGetSymbolAddress((void**)&tw2t, g_tw2t);
    cudaGetSymbolAddress((void**)&mw1t, g_mw1t);
    cudaGetSymbolAddress((void**)&mw2t, g_mw2t);
    cudaGetSymbolAddress((void**)&mw3t, g_mw3t);
    cudaGetSymbolAddress((void**)&hn,   g_hn);
    cudaGetSymbolAddress((void**)&yn,   g_yn);

    dim3 blk(16, 16);

    // weight transposes
    wtrans_k<<<(384 * ADIM * 3 + 255) / 256, 256>>>(t_w1, tw1t, ADIM, 3);
    wtrans_k<<<(384 * ADIM * 1 + 255) / 256, 256>>>(t_w2, tw2t, ADIM, 1);
    wtrans_k<<<(384 * ODIM * 3 + 255) / 256, 256>>>(m_w1, mw1t, ODIM, 3);
    wtrans_k<<<(384 * ADIM * 3 + 255) / 256, 256>>>(m_w2, mw2t, ADIM, 3);
    wtrans_k<<<(384 * ADIM * 1 + 255) / 256, 256>>>(m_w3, mw3t, ADIM, 1);

    // text prenet
    {
        dim3 g((TTEXT + 63) / 64, 6, BB);
        conv1d_k<ADIM, 3, true ><<<g, blk>>>(hs, tw1t, t_b1, h1, TTEXT);
        conv1d_k<ADIM, 1, false><<<g, blk>>>(h1, tw2t, t_b2, h2, TTEXT);
    }
    // mel prenet
    {
        dim3 g((TMEL + 63) / 64, 6, BB);
        conv1d_k<ODIM, 3, true ><<<g, blk>>>(ys, mw1t, m_b1, y1, TMEL);
        conv1d_k<ADIM, 3, true ><<<g, blk>>>(y1, mw2t, m_b2, y2, TMEL);
        conv1d_k<ADIM, 1, false><<<g, blk>>>(y2, mw3t, m_b3, y1, TMEL);
    }

    // row norms
    rownorm_k<<<BB * TTEXT, 128>>>(h2, hn);
    rownorm_k<<<BB * TMEL, 128>>>(y1, yn);

    // fused distance + log_softmax
    {
        dim3 g(TMEL / 64, BB);
        attn_k<<<g, blk>>>(y1, h2, yn, hn, mask, out);
    }
}

// round 3
// speedup vs baseline: 1.7083x; 1.7083x over previous
#include <cuda_runtime.h>
#include <math.h>

#define BB    32
#define TTEXT 400
#define TMEL  1600
#define ADIM  384
#define ODIM  80

// ---------------- static scratch (no allocations allowed) ----------------
__device__ float g_h1[(size_t)BB * TTEXT * ADIM];
__device__ float g_h2[(size_t)BB * TTEXT * ADIM];
__device__ float g_y1[(size_t)BB * TMEL * ADIM];
__device__ float g_y2[(size_t)BB * TMEL * ADIM];
__device__ float g_tw1t[3 * ADIM * ADIM];
__device__ float g_tw2t[1 * ADIM * ADIM];
__device__ float g_mw1t[3 * ODIM * ADIM];
__device__ float g_mw2t[3 * ADIM * ADIM];
__device__ float g_mw3t[1 * ADIM * ADIM];
__device__ float g_hn[BB * TTEXT];
__device__ float g_yn[BB * TMEL];

// ---------------- packed f32x2 helpers (sm_100+) ----------------
__device__ __forceinline__ unsigned long long ffma2(unsigned long long a,
                                                    unsigned long long b,
                                                    unsigned long long c)
{
    unsigned long long d;
    asm("fma.rn.f32x2 %0, %1, %2, %3;" : "=l"(d) : "l"(a), "l"(b), "l"(c));
    return d;
}
__device__ __forceinline__ unsigned long long pack2(float lo, float hi)
{
    unsigned long long d;
    asm("mov.b64 %0, {%1, %2};" : "=l"(d) : "f"(lo), "f"(hi));
    return d;
}
__device__ __forceinline__ float2 unpack2(unsigned long long v)
{
    float2 r;
    asm("mov.b64 {%0, %1}, %2;" : "=f"(r.x), "=f"(r.y) : "l"(v));
    return r;
}

// ---------------- weight transpose: W[co][ci][k] -> Wt[k][ci][co] ----------------
__global__ void wtrans_k(const float* __restrict__ W, float* __restrict__ Wt,
                         int CIN, int K)
{
    int idx = blockIdx.x * 256 + threadIdx.x;
    int total = 384 * CIN * K;
    if (idx >= total) return;
    int k  = idx % K;
    int ci = (idx / K) % CIN;
    int co = idx / (K * CIN);
    Wt[((size_t)k * CIN + ci) * 384 + co] = W[idx];
}

// ---------------- conv1d as tiled GEMM over taps (f32x2 math) ----------------
// X: [B, T, CIN] (time-major), Wt: [K][CIN][384], Out: [B, T, 384]
// grid: (ceil(T/128), 6, B), block (16,16), thread microtile 8 rows x 4 couts.
template<int CIN, int KS, bool RELU>
__global__ __launch_bounds__(256)
void conv1d_k(const float* __restrict__ X, const float* __restrict__ Wt,
              const float* __restrict__ bias, float* __restrict__ Out, int T)
{
    constexpr int PAD   = (KS - 1) / 2;
    constexpr int TT    = 128;
    constexpr int XROWS = TT + KS - 1;
    constexpr int XR    = 8 + KS - 1;
    __shared__ float Xs[XROWS][20];          // pad 20 -> 16B-aligned float4 rows
    __shared__ float Ws[KS][16][64];

    const int b  = blockIdx.z;
    const int t0 = blockIdx.x * TT;
    const int n0 = blockIdx.y * 64;
    const int tx = threadIdx.x, ty = threadIdx.y;
    const int tid = ty * 16 + tx;
    const float* Xb = X + (size_t)b * T * CIN;

    unsigned long long acc[8][2];
    #pragma unroll
    for (int r = 0; r < 8; r++) { acc[r][0] = 0ull; acc[r][1] = 0ull; }

    for (int kc = 0; kc < CIN; kc += 16) {
        // X halo tile, float4 fills, zero-padded at edges
        #pragma unroll
        for (int i = tid; i < XROWS * 4; i += 256) {
            int r = i >> 2, c4 = (i & 3) * 4;
            int t = t0 + r - PAD;
            float4 v = make_float4(0.f, 0.f, 0.f, 0.f);
            if (t >= 0 && t < T)
                v = *(const float4*)&Xb[(size_t)t * CIN + kc + c4];
            *(float4*)&Xs[r][c4] = v;
        }
        // weight tile, float4 fills (coalesced in co)
        #pragma unroll
        for (int i = tid; i < KS * 16 * 16; i += 256) {
            int k   = i / 256;
            int rem = i & 255;
            int c = rem >> 4, n4 = (rem & 15) * 4;
            *(float4*)&Ws[k][c][n4] =
                *(const float4*)&Wt[((size_t)k * CIN + kc + c) * 384 + n0 + n4];
        }
        __syncthreads();

        #pragma unroll
        for (int kk = 0; kk < 16; kk++) {
            unsigned long long xd[XR];
            #pragma unroll
            for (int r = 0; r < XR; r++) {
                float x = Xs[ty * 8 + r][kk];
                xd[r] = pack2(x, x);
            }
            #pragma unroll
            for (int k = 0; k < KS; k++) {
                ulonglong2 w = *(const ulonglong2*)&Ws[k][kk][tx * 4];
                #pragma unroll
                for (int r = 0; r < 8; r++) {
                    acc[r][0] = ffma2(xd[r + k], w.x, acc[r][0]);
                    acc[r][1] = ffma2(xd[r + k], w.y, acc[r][1]);
                }
            }
        }
        __syncthreads();
    }

    float4 bb = *(const float4*)&bias[n0 + tx * 4];
    #pragma unroll
    for (int r = 0; r < 8; r++) {
        int t = t0 + ty * 8 + r;
        if (t < T) {
            float2 a0 = unpack2(acc[r][0]);
            float2 a1 = unpack2(acc[r][1]);
            float4 v;
            v.x = a0.x + bb.x; v.y = a0.y + bb.y;
            v.z = a1.x + bb.z; v.w = a1.y + bb.w;
            if (RELU) {
                v.x = fmaxf(v.x, 0.f); v.y = fmaxf(v.y, 0.f);
                v.z = fmaxf(v.z, 0.f); v.w = fmaxf(v.w, 0.f);
            }
            *(float4*)&Out[((size_t)b * T + t) * 384 + n0 + tx * 4] = v;
        }
    }
}

// ---------------- row squared-norms over 384 features ----------------
__global__ void rownorm_k(const float* __restrict__ X, float* __restrict__ Nrm)
{
    int row = blockIdx.x;
    const float* p = X + (size_t)row * 384;
    float s = 0.f;
    for (int i = threadIdx.x; i < 384; i += 128) { float v = p[i]; s += v * v; }
    #pragma unroll
    for (int o = 16; o > 0; o >>= 1) s += __shfl_xor_sync(0xffffffffu, s, o);
    __shared__ float ps[4];
    if ((threadIdx.x & 31) == 0) ps[threadIdx.x >> 5] = s;
    __syncthreads();
    if (threadIdx.x == 0) Nrm[row] = ps[0] + ps[1] + ps[2] + ps[3];
}

// ---------------- fused distance GEMM + sqrt + mask + log_softmax ----------------
// Y: [B,1600,384], H: [B,400,384]. Out: [B,1600,400].
// grid: (1600/64, B), block (16,16). Each thread: 4 mel rows x 25 text cols
// (12 f32x2 pairs + 1 scalar).
__global__ __launch_bounds__(256)
void attn_k(const float* __restrict__ Y, const float* __restrict__ H,
            const float* __restrict__ Yn, const float* __restrict__ Hn,
            const unsigned char* __restrict__ mask, float* __restrict__ Out)
{
    const int b  = blockIdx.y;
    const int m0 = blockIdx.x * 64;
    const int tx = threadIdx.x, ty = threadIdx.y;
    const int tid = ty * 16 + tx;

    __shared__ float Hs[400][17];    // 17: conflict-free for stride-17*tx reads
    __shared__ float Ysm[64][20];    // 20: 16B-aligned float4 fills, ty-broadcast reads
    __shared__ float sHn[400];
    __shared__ unsigned char sM[400];

    const float* Hb = H + (size_t)b * TTEXT * ADIM;
    const float* Yb = Y + ((size_t)b * TMEL + m0) * ADIM;

    for (int i = tid; i < 400; i += 256) {
        sHn[i] = Hn[b * TTEXT + i];
        sM[i]  = mask[b * TTEXT + i];
    }

    unsigned long long s2[4][12];
    float s1[4];
    #pragma unroll
    for (int r = 0; r < 4; r++) {
        s1[r] = 0.f;
        #pragma unroll
        for (int j = 0; j < 12; j++) s2[r][j] = 0ull;
    }

    for (int kc = 0; kc < ADIM; kc += 16) {
        for (int i = tid; i < 400 * 16; i += 256) {
            int r = i >> 4, c = i & 15;
            Hs[r][c] = Hb[(size_t)r * ADIM + kc + c];
        }
        #pragma unroll
        for (int i = tid; i < 64 * 4; i += 256) {
            int r = i >> 2, c4 = (i & 3) * 4;
            *(float4*)&Ysm[r][c4] = *(const float4*)&Yb[(size_t)r * ADIM + kc + c4];
        }
        __syncthreads();

        #pragma unroll
        for (int kk = 0; kk < 16; kk++) {
            float yv[4];
            unsigned long long yd[4];
            #pragma unroll
            for (int r = 0; r < 4; r++) {
                yv[r] = Ysm[ty * 4 + r][kk];
                yd[r] = pack2(yv[r], yv[r]);
            }
            #pragma unroll
            for (int j = 0; j < 12; j++) {
                unsigned long long hp =
                    pack2(Hs[tx + 32 * j][kk], Hs[tx + 32 * j + 16][kk]);
                #pragma unroll
                for (int r = 0; r < 4; r++) s2[r][j] = ffma2(yd[r], hp, s2[r][j]);
            }
            float hl = Hs[tx + 384][kk];
            #pragma unroll
            for (int r = 0; r < 4; r++) s1[r] += yv[r] * hl;
        }
        __syncthreads();
    }

    // epilogue: score = -sqrt(max(||y||^2 + ||h||^2 - 2*dot, 1e-12)), log_softmax
    #pragma unroll
    for (int r = 0; r < 4; r++) {
        float s[25];
        #pragma unroll
        for (int j = 0; j < 12; j++) {
            float2 p = unpack2(s2[r][j]);
            s[2 * j]     = p.x;   // col tx + 16*(2j)
            s[2 * j + 1] = p.y;   // col tx + 16*(2j+1)
        }
        s[24] = s1[r];

        int m = m0 + ty * 4 + r;
        float yn = Yn[b * TMEL + m];
        float mx = -INFINITY;
        #pragma unroll
        for (int j = 0; j < 25; j++) {
            int t = tx + 16 * j;
            float sq = yn + sHn[t] - 2.f * s[j];
            float d  = sqrtf(fmaxf(sq, 1e-12f));
            float sc = sM[t] ? -INFINITY : -d;
            s[j] = sc;
            mx = fmaxf(mx, sc);
        }
        #pragma unroll
        for (int o = 8; o > 0; o >>= 1)
            mx = fmaxf(mx, __shfl_xor_sync(0xffffffffu, mx, o, 16));
        float sum = 0.f;
        #pragma unroll
        for (int j = 0; j < 25; j++) sum += __expf(s[j] - mx);
        #pragma unroll
        for (int o = 8; o > 0; o >>= 1)
            sum += __shfl_xor_sync(0xffffffffu, sum, o, 16);
        float lse = mx + __logf(sum);
        float* op = Out + ((size_t)b * TMEL + m) * TTEXT;
        #pragma unroll
        for (int j = 0; j < 25; j++) op[tx + 16 * j] = s[j] - lse;
    }
}

// ---------------- launch ----------------
extern "C" void kernel_launch(void* const* d_in, const int* in_sizes, int n_in,
                              void* d_out, int out_size)
{
    const float* hs   = (const float*)d_in[0];
    const float* ys   = (const float*)d_in[1];
    const unsigned char* mask = (const unsigned char*)d_in[2];
    const float* t_w1 = (const float*)d_in[3];
    const float* t_b1 = (const float*)d_in[4];
    const float* t_w2 = (const float*)d_in[5];
    const float* t_b2 = (const float*)d_in[6];
    const float* m_w1 = (const float*)d_in[7];
    const float* m_b1 = (const float*)d_in[8];
    const float* m_w2 = (const float*)d_in[9];
    const float* m_b2 = (const float*)d_in[10];
    const float* m_w3 = (const float*)d_in[11];
    const float* m_b3 = (const float*)d_in[12];
    float* out = (float*)d_out;

    float *h1, *h2, *y1, *y2, *tw1t, *tw2t, *mw1t, *mw2t, *mw3t, *hn, *yn;
    cudaGetSymbolAddress((void**)&h1,   g_h1);
    cudaGetSymbolAddress((void**)&h2,   g_h2);
    cudaGetSymbolAddress((void**)&y1,   g_y1);
    cudaGetSymbolAddress((void**)&y2,   g_y2);
    cudaGetSymbolAddress((void**)&tw1t, g_tw1t);
    cudaGetSymbolAddress((void**)&tw2t, g_tw2t);
    cudaGetSymbolAddress((void**)&mw1t, g_mw1t);
    cudaGetSymbolAddress((void**)&mw2t, g_mw2t);
    cudaGetSymbolAddress((void**)&mw3t, g_mw3t);
    cudaGetSymbolAddress((void**)&hn,   g_hn);
    cudaGetSymbolAddress((void**)&yn,   g_yn);

    dim3 blk(16, 16);

    // weight transposes
    wtrans_k<<<(384 * ADIM * 3 + 255) / 256, 256>>>(t_w1, tw1t, ADIM, 3);
    wtrans_k<<<(384 * ADIM * 1 + 255) / 256, 256>>>(t_w2, tw2t, ADIM, 1);
    wtrans_k<<<(384 * ODIM * 3 + 255) / 256, 256>>>(m_w1, mw1t, ODIM, 3);
    wtrans_k<<<(384 * ADIM * 3 + 255) / 256, 256>>>(m_w2, mw2t, ADIM, 3);
    wtrans_k<<<(384 * ADIM * 1 + 255) / 256, 256>>>(m_w3, mw3t, ADIM, 1);

    // text prenet
    {
        dim3 g((TTEXT + 127) / 128, 6, BB);
        conv1d_k<ADIM, 3, true ><<<g, blk>>>(hs, tw1t, t_b1, h1, TTEXT);
        conv1d_k<ADIM, 1, false><<<g, blk>>>(h1, tw2t, t_b2, h2, TTEXT);
    }
    // mel prenet
    {
        dim3 g((TMEL + 127) / 128, 6, BB);
        conv1d_k<ODIM, 3, true ><<<g, blk>>>(ys, mw1t, m_b1, y1, TMEL);
        conv1d_k<ADIM, 3, true ><<<g, blk>>>(y1, mw2t, m_b2, y2, TMEL);
        conv1d_k<ADIM, 1, false><<<g, blk>>>(y2, mw3t, m_b3, y1, TMEL);
    }

    // row norms
    rownorm_k<<<BB * TTEXT, 128>>>(h2, hn);
    rownorm_k<<<BB * TMEL, 128>>>(y1, yn);

    // fused distance + log_softmax
    {
        dim3 g(TMEL / 64, BB);
        attn_k<<<g, blk>>>(y1, h2, yn, hn, mask, out);
    }
}

// round 4
// speedup vs baseline: 2.0791x; 1.2170x over previous
#include <cuda_runtime.h>
#include <math.h>

#define BB    32
#define TTEXT 400
#define TMEL  1600
#define ADIM  384
#define ODIM  80

// ---------------- static scratch (no allocations allowed) ----------------
__device__ float g_h1[(size_t)BB * TTEXT * ADIM];
__device__ float g_h2[(size_t)BB * TTEXT * ADIM];
__device__ float g_y1[(size_t)BB * TMEL * ADIM];
__device__ float g_y2[(size_t)BB * TMEL * ADIM];
__device__ float g_tw1t[3 * ADIM * ADIM];
__device__ float g_tw2t[1 * ADIM * ADIM];
__device__ float g_mw1t[3 * ODIM * ADIM];
__device__ float g_mw2t[3 * ADIM * ADIM];
__device__ float g_mw3t[1 * ADIM * ADIM];
__device__ float g_hn[BB * TTEXT];
__device__ float g_yn[BB * TMEL];

// ---------------- packed f32x2 + async-copy helpers ----------------
__device__ __forceinline__ unsigned long long ffma2(unsigned long long a,
                                                    unsigned long long b,
                                                    unsigned long long c)
{
    unsigned long long d;
    asm("fma.rn.f32x2 %0, %1, %2, %3;" : "=l"(d) : "l"(a), "l"(b), "l"(c));
    return d;
}
__device__ __forceinline__ unsigned long long pack2(float lo, float hi)
{
    unsigned long long d;
    asm("mov.b64 %0, {%1, %2};" : "=l"(d) : "f"(lo), "f"(hi));
    return d;
}
__device__ __forceinline__ float2 unpack2(unsigned long long v)
{
    float2 r;
    asm("mov.b64 {%0, %1}, %2;" : "=f"(r.x), "=f"(r.y) : "l"(v));
    return r;
}
__device__ __forceinline__ unsigned int sm_addr(const void* p)
{
    return (unsigned int)__cvta_generic_to_shared(p);
}
__device__ __forceinline__ void cp16(unsigned int dst, const void* src,
                                     unsigned int bytes)
{
    asm volatile("cp.async.cg.shared.global [%0], [%1], 16, %2;"
                 :: "r"(dst), "l"(src), "r"(bytes) : "memory");
}
__device__ __forceinline__ void cp_commit()
{
    asm volatile("cp.async.commit_group;" ::: "memory");
}
template<int N>
__device__ __forceinline__ void cp_wait()
{
    asm volatile("cp.async.wait_group %0;" :: "n"(N) : "memory");
}

// ---------------- weight transpose: W[co][ci][k] -> Wt[k][ci][co] ----------------
__global__ void wtrans_k(const float* __restrict__ W, float* __restrict__ Wt,
                         int CIN, int K)
{
    int idx = blockIdx.x * 256 + threadIdx.x;
    int total = 384 * CIN * K;
    if (idx >= total) return;
    int k  = idx % K;
    int ci = (idx / K) % CIN;
    int co = idx / (K * CIN);
    Wt[((size_t)k * CIN + ci) * 384 + co] = W[idx];
}

// ---------------- conv1d as tiled GEMM over taps (f32x2, cp.async 2-stage) ----
// X: [B, T, CIN] time-major, Wt: [K][CIN][384], Out: [B, T, 384]
// grid: (ceil(T/128), 6, B), block (16,16), microtile 8 rows x 4 couts.
template<int CIN, int KS, bool RELU>
__global__ __launch_bounds__(256)
void conv1d_k(const float* __restrict__ X, const float* __restrict__ Wt,
              const float* __restrict__ bias, float* __restrict__ Out, int T)
{
    constexpr int PAD   = (KS - 1) / 2;
    constexpr int TT    = 128;
    constexpr int XROWS = TT + KS - 1;
    constexpr int XR    = 8 + KS - 1;
    constexpr int NCH   = CIN / 16;
    __shared__ float Xs[2][XROWS][20];       // row = 80B (16B-aligned)
    __shared__ float Ws[2][KS][16][64];

    const int b  = blockIdx.z;
    const int t0 = blockIdx.x * TT;
    const int n0 = blockIdx.y * 64;
    const int tx = threadIdx.x, ty = threadIdx.y;
    const int tid = ty * 16 + tx;
    const float* Xb = X + (size_t)b * T * CIN;

    // async fill of one k-chunk into stage buf
    auto issue = [&](int ch, int buf) {
        int kc = ch * 16;
        #pragma unroll
        for (int i = tid; i < XROWS * 4; i += 256) {
            int r = i >> 2, c4 = (i & 3) * 4;
            int t = t0 + r - PAD;
            int tc = t < 0 ? 0 : (t >= T ? T - 1 : t);
            unsigned int ok = (t >= 0 && t < T) ? 16u : 0u;
            cp16(sm_addr(&Xs[buf][r][c4]),
                 &Xb[(size_t)tc * CIN + kc + c4], ok);
        }
        #pragma unroll
        for (int i = tid; i < KS * 256; i += 256) {
            int k   = i >> 8;
            int rem = i & 255;
            int c = rem >> 4, n4 = (rem & 15) * 4;
            cp16(sm_addr(&Ws[buf][k][c][n4]),
                 &Wt[((size_t)k * CIN + kc + c) * 384 + n0 + n4], 16u);
        }
        cp_commit();
    };

    unsigned long long acc[8][2];
    #pragma unroll
    for (int r = 0; r < 8; r++) { acc[r][0] = 0ull; acc[r][1] = 0ull; }

    issue(0, 0);
    for (int ch = 0; ch < NCH; ch++) {
        int buf = ch & 1;
        if (ch + 1 < NCH) { issue(ch + 1, buf ^ 1); cp_wait<1>(); }
        else              { cp_wait<0>(); }
        __syncthreads();

        #pragma unroll
        for (int kk = 0; kk < 16; kk++) {
            unsigned long long xd[XR];
            #pragma unroll
            for (int r = 0; r < XR; r++) {
                float x = Xs[buf][ty * 8 + r][kk];
                xd[r] = pack2(x, x);
            }
            #pragma unroll
            for (int k = 0; k < KS; k++) {
                ulonglong2 w = *(const ulonglong2*)&Ws[buf][k][kk][tx * 4];
                #pragma unroll
                for (int r = 0; r < 8; r++) {
                    acc[r][0] = ffma2(xd[r + k], w.x, acc[r][0]);
                    acc[r][1] = ffma2(xd[r + k], w.y, acc[r][1]);
                }
            }
        }
        __syncthreads();
    }

    float4 bb = *(const float4*)&bias[n0 + tx * 4];
    #pragma unroll
    for (int r = 0; r < 8; r++) {
        int t = t0 + ty * 8 + r;
        if (t < T) {
            float2 a0 = unpack2(acc[r][0]);
            float2 a1 = unpack2(acc[r][1]);
            float4 v;
            v.x = a0.x + bb.x; v.y = a0.y + bb.y;
            v.z = a1.x + bb.z; v.w = a1.y + bb.w;
            if (RELU) {
                v.x = fmaxf(v.x, 0.f); v.y = fmaxf(v.y, 0.f);
                v.z = fmaxf(v.z, 0.f); v.w = fmaxf(v.w, 0.f);
            }
            *(float4*)&Out[((size_t)b * T + t) * 384 + n0 + tx * 4] = v;
        }
    }
}

// ---------------- row squared-norms over 384 features ----------------
__global__ void rownorm_k(const float* __restrict__ X, float* __restrict__ Nrm)
{
    int row = blockIdx.x;
    const float* p = X + (size_t)row * 384;
    float s = 0.f;
    for (int i = threadIdx.x; i < 384; i += 128) { float v = p[i]; s += v * v; }
    #pragma unroll
    for (int o = 16; o > 0; o >>= 1) s += __shfl_xor_sync(0xffffffffu, s, o);
    __shared__ float ps[4];
    if ((threadIdx.x & 31) == 0) ps[threadIdx.x >> 5] = s;
    __syncthreads();
    if (threadIdx.x == 0) Nrm[row] = ps[0] + ps[1] + ps[2] + ps[3];
}

// ---------------- fused distance GEMM + sqrt + mask + log_softmax ----------------
// Y: [B,1600,384], H: [B,400,384]. Out: [B,1600,400].
// grid: (1600/64, B), block (16,16). Thread: 4 mel rows x (12 col-pairs + 1).
// H stored pre-paired in smem (u64 = cols {2p, 2p+1}) -> LDS.64, no packs.
// 2-stage register-staged pipeline over k-chunks of 8.
__global__ __launch_bounds__(256)
void attn_k(const float* __restrict__ Y, const float* __restrict__ H,
            const float* __restrict__ Yn, const float* __restrict__ Hn,
            const unsigned char* __restrict__ mask, float* __restrict__ Out)
{
    constexpr int CK = 8;
    constexpr int NC = ADIM / CK;          // 48
    const int b  = blockIdx.y;
    const int m0 = blockIdx.x * 64;
    const int tx = threadIdx.x, ty = threadIdx.y;
    const int tid = ty * 16 + tx;

    __shared__ unsigned long long Hs[2][192][9];  // pairs, pad 9: conflict-free
    __shared__ float HsL[2][16][9];               // leftover cols 384..399
    __shared__ float Ysm[2][64][12];              // pad 12 -> 48B rows
    __shared__ float sHn[400];
    __shared__ unsigned char sM[400];

    const float* Hb = H + (size_t)b * TTEXT * ADIM;
    const float* Yb = Y + ((size_t)b * TMEL + m0) * ADIM;

    for (int i = tid; i < 400; i += 256) {
        sHn[i] = Hn[b * TTEXT + i];
        sM[i]  = mask[b * TTEXT + i];
    }

    // staging registers
    float4 hA1, hB1, hA2, hB2;   // Hs task(s): two H rows x float4
    float4 hL;                   // HsL task (tid < 32)
    float4 yS;                   // Ys task (tid >= 128)

    auto load_regs = [&](int ch) {
        int kc = ch * CK;
        {   // Hs task 1: task id = tid (0..255), p = task>>1, c4 = (task&1)*4
            int p = tid >> 1, c4 = (tid & 1) * 4;
            hA1 = *(const float4*)&Hb[(size_t)(2 * p)     * ADIM + kc + c4];
            hB1 = *(const float4*)&Hb[(size_t)(2 * p + 1) * ADIM + kc + c4];
        }
        if (tid < 128) {  // Hs task 2: task id = 256 + tid
            int t2 = 256 + tid;
            int p = t2 >> 1, c4 = (t2 & 1) * 4;
            hA2 = *(const float4*)&Hb[(size_t)(2 * p)     * ADIM + kc + c4];
            hB2 = *(const float4*)&Hb[(size_t)(2 * p + 1) * ADIM + kc + c4];
        }
        if (tid < 32) {   // leftover rows 384+l
            int l = tid >> 1, c4 = (tid & 1) * 4;
            hL = *(const float4*)&Hb[(size_t)(384 + l) * ADIM + kc + c4];
        }
        if (tid >= 128) { // Ys: i = tid-128, r = i>>1, c4 = (i&1)*4
            int i = tid - 128;
            int r = i >> 1, c4 = (i & 1) * 4;
            yS = *(const float4*)&Yb[(size_t)r * ADIM + kc + c4];
        }
    };
    auto store_smem = [&](int buf) {
        {
            int p = tid >> 1, c4 = (tid & 1) * 4;
            Hs[buf][p][c4 + 0] = pack2(hA1.x, hB1.x);
            Hs[buf][p][c4 + 1] = pack2(hA1.y, hB1.y);
            Hs[buf][p][c4 + 2] = pack2(hA1.z, hB1.z);
            Hs[buf][p][c4 + 3] = pack2(hA1.w, hB1.w);
        }
        if (tid < 128) {
            int t2 = 256 + tid;
            int p = t2 >> 1, c4 = (t2 & 1) * 4;
            Hs[buf][p][c4 + 0] = pack2(hA2.x, hB2.x);
            Hs[buf][p][c4 + 1] = pack2(hA2.y, hB2.y);
            Hs[buf][p][c4 + 2] = pack2(hA2.z, hB2.z);
            Hs[buf][p][c4 + 3] = pack2(hA2.w, hB2.w);
        }
        if (tid < 32) {
            int l = tid >> 1, c4 = (tid & 1) * 4;
            HsL[buf][l][c4 + 0] = hL.x; HsL[buf][l][c4 + 1] = hL.y;
            HsL[buf][l][c4 + 2] = hL.z; HsL[buf][l][c4 + 3] = hL.w;
        }
        if (tid >= 128) {
            int i = tid - 128;
            int r = i >> 1, c4 = (i & 1) * 4;
            *(float4*)&Ysm[buf][r][c4] = yS;
        }
    };

    unsigned long long s2[4][12];
    float s1[4];
    #pragma unroll
    for (int r = 0; r < 4; r++) {
        s1[r] = 0.f;
        #pragma unroll
        for (int j = 0; j < 12; j++) s2[r][j] = 0ull;
    }

    load_regs(0);
    for (int ch = 0; ch < NC; ch++) {
        int buf = ch & 1;
        store_smem(buf);
        __syncthreads();
        if (ch + 1 < NC) load_regs(ch + 1);

        #pragma unroll
        for (int kk = 0; kk < CK; kk++) {
            float yv[4];
            unsigned long long yd[4];
            #pragma unroll
            for (int r = 0; r < 4; r++) {
                yv[r] = Ysm[buf][ty * 4 + r][kk];
                yd[r] = pack2(yv[r], yv[r]);
            }
            #pragma unroll
            for (int j = 0; j < 12; j++) {
                unsigned long long hp = Hs[buf][tx + 16 * j][kk];
                #pragma unroll
                for (int r = 0; r < 4; r++) s2[r][j] = ffma2(yd[r], hp, s2[r][j]);
            }
            float hl = HsL[buf][tx][kk];
            #pragma unroll
            for (int r = 0; r < 4; r++) s1[r] += yv[r] * hl;
        }
        __syncthreads();
    }

    // epilogue: score = -sqrt(max(||y||^2+||h||^2-2dot,1e-12)), log_softmax
    #pragma unroll
    for (int r = 0; r < 4; r++) {
        float s[25];
        #pragma unroll
        for (int j = 0; j < 12; j++) {
            float2 p = unpack2(s2[r][j]);
            s[2 * j]     = p.x;   // col 2*(tx+16j)
            s[2 * j + 1] = p.y;   // col 2*(tx+16j)+1
        }
        s[24] = s1[r];            // col 384+tx

        int m = m0 + ty * 4 + r;
        float yn = Yn[b * TMEL + m];
        float mx = -INFINITY;
        #pragma unroll
        for (int j = 0; j < 25; j++) {
            int t = (j < 24) ? (2 * (tx + 16 * (j >> 1)) + (j & 1)) : (384 + tx);
            float sq = yn + sHn[t] - 2.f * s[j];
            float d  = sqrtf(fmaxf(sq, 1e-12f));
            float sc = sM[t] ? -INFINITY : -d;
            s[j] = sc;
            mx = fmaxf(mx, sc);
        }
        #pragma unroll
        for (int o = 8; o > 0; o >>= 1)
            mx = fmaxf(mx, __shfl_xor_sync(0xffffffffu, mx, o, 16));
        float sum = 0.f;
        #pragma unroll
        for (int j = 0; j < 25; j++) sum += __expf(s[j] - mx);
        #pragma unroll
        for (int o = 8; o > 0; o >>= 1)
            sum += __shfl_xor_sync(0xffffffffu, sum, o, 16);
        float lse = mx + __logf(sum);
        float* op = Out + ((size_t)b * TMEL + m) * TTEXT;
        #pragma unroll
        for (int j = 0; j < 12; j++) {
            float2 v = make_float2(s[2 * j] - lse, s[2 * j + 1] - lse);
            *(float2*)&op[2 * (tx + 16 * j)] = v;
        }
        op[384 + tx] = s[24] - lse;
    }
}

// ---------------- launch ----------------
extern "C" void kernel_launch(void* const* d_in, const int* in_sizes, int n_in,
                              void* d_out, int out_size)
{
    const float* hs   = (const float*)d_in[0];
    const float* ys   = (const float*)d_in[1];
    const unsigned char* mask = (const unsigned char*)d_in[2];
    const float* t_w1 = (const float*)d_in[3];
    const float* t_b1 = (const float*)d_in[4];
    const float* t_w2 = (const float*)d_in[5];
    const float* t_b2 = (const float*)d_in[6];
    const float* m_w1 = (const float*)d_in[7];
    const float* m_b1 = (const float*)d_in[8];
    const float* m_w2 = (const float*)d_in[9];
    const float* m_b2 = (const float*)d_in[10];
    const float* m_w3 = (const float*)d_in[11];
    const float* m_b3 = (const float*)d_in[12];
    float* out = (float*)d_out;

    float *h1, *h2, *y1, *y2, *tw1t, *tw2t, *mw1t, *mw2t, *mw3t, *hn, *yn;
    cudaGetSymbolAddress((void**)&h1,   g_h1);
    cudaGetSymbolAddress((void**)&h2,   g_h2);
    cudaGetSymbolAddress((void**)&y1,   g_y1);
    cudaGetSymbolAddress((void**)&y2,   g_y2);
    cudaGetSymbolAddress((void**)&tw1t, g_tw1t);
    cudaGetSymbolAddress((void**)&tw2t, g_tw2t);
    cudaGetSymbolAddress((void**)&mw1t, g_mw1t);
    cudaGetSymbolAddress((void**)&mw2t, g_mw2t);
    cudaGetSymbolAddress((void**)&mw3t, g_mw3t);
    cudaGetSymbolAddress((void**)&hn,   g_hn);
    cudaGetSymbolAddress((void**)&yn,   g_yn);

    dim3 blk(16, 16);

    // weight transposes
    wtrans_k<<<(384 * ADIM * 3 + 255) / 256, 256>>>(t_w1, tw1t, ADIM, 3);
    wtrans_k<<<(384 * ADIM * 1 + 255) / 256, 256>>>(t_w2, tw2t, ADIM, 1);
    wtrans_k<<<(384 * ODIM * 3 + 255) / 256, 256>>>(m_w1, mw1t, ODIM, 3);
    wtrans_k<<<(384 * ADIM * 3 + 255) / 256, 256>>>(m_w2, mw2t, ADIM, 3);
    wtrans_k<<<(384 * ADIM * 1 + 255) / 256, 256>>>(m_w3, mw3t, ADIM, 1);

    // text prenet
    {
        dim3 g((TTEXT + 127) / 128, 6, BB);
        conv1d_k<ADIM, 3, true ><<<g, blk>>>(hs, tw1t, t_b1, h1, TTEXT);
        conv1d_k<ADIM, 1, false><<<g, blk>>>(h1, tw2t, t_b2, h2, TTEXT);
    }
    // mel prenet
    {
        dim3 g((TMEL + 127) / 128, 6, BB);
        conv1d_k<ODIM, 3, true ><<<g, blk>>>(ys, mw1t, m_b1, y1, TMEL);
        conv1d_k<ADIM, 3, true ><<<g, blk>>>(y1, mw2t, m_b2, y2, TMEL);
        conv1d_k<ADIM, 1, false><<<g, blk>>>(y2, mw3t, m_b3, y1, TMEL);
    }

    // row norms
    rownorm_k<<<BB * TTEXT, 128>>>(h2, hn);
    rownorm_k<<<BB * TMEL, 128>>>(y1, yn);

    // fused distance + log_softmax
    {
        dim3 g(TMEL / 64, BB);
        attn_k<<<g, blk>>>(y1, h2, yn, hn, mask, out);
    }
}

// round 6
// speedup vs baseline: 3.3841x; 1.6277x over previous
#include <cuda_runtime.h>
#include <cuda_bf16.h>
#include <math.h>
#include <stdint.h>

#define BB    32
#define TTEXT 400
#define TMEL  1600
#define ADIM  384
#define ODIM  80
#define CIPM  128   // mel input channels padded 80 -> 128

// ---------------- static scratch (no allocations allowed) ----------------
__device__ __nv_bfloat16 g_xht[(size_t)BB * TTEXT * ADIM];
__device__ __nv_bfloat16 g_xlt[(size_t)BB * TTEXT * ADIM];
__device__ __nv_bfloat16 g_h1h[(size_t)BB * TTEXT * ADIM];
__device__ __nv_bfloat16 g_h1l[(size_t)BB * TTEXT * ADIM];
__device__ __nv_bfloat16 g_xhm[(size_t)BB * TMEL * CIPM];
__device__ __nv_bfloat16 g_xlm[(size_t)BB * TMEL * CIPM];
__device__ __nv_bfloat16 g_y1h[(size_t)BB * TMEL * ADIM];
__device__ __nv_bfloat16 g_y1l[(size_t)BB * TMEL * ADIM];
__device__ __nv_bfloat16 g_y2h[(size_t)BB * TMEL * ADIM];
__device__ __nv_bfloat16 g_y2l[(size_t)BB * TMEL * ADIM];
// weights bf16 hi/lo, layout [k][co][ci_padded]
__device__ __nv_bfloat16 g_wt1h[3 * 384 * ADIM], g_wt1l[3 * 384 * ADIM];
__device__ __nv_bfloat16 g_wt2h[1 * 384 * ADIM], g_wt2l[1 * 384 * ADIM];
__device__ __nv_bfloat16 g_wm1h[3 * 384 * CIPM], g_wm1l[3 * 384 * CIPM];
__device__ __nv_bfloat16 g_wm2h[3 * 384 * ADIM], g_wm2l[3 * 384 * ADIM];
__device__ __nv_bfloat16 g_wm3h[1 * 384 * ADIM], g_wm3l[1 * 384 * ADIM];
// fp32 finals + norms
__device__ float g_h2[(size_t)BB * TTEXT * ADIM];
__device__ float g_y1[(size_t)BB * TMEL * ADIM];
__device__ float g_hn[BB * TTEXT];
__device__ float g_yn[BB * TMEL];

// ---------------- PTX helpers (family-level only: sm_80/90 era) ----------------
__device__ __forceinline__ unsigned long long ffma2(unsigned long long a,
                                                    unsigned long long b,
                                                    unsigned long long c)
{
    unsigned long long d;
    asm("fma.rn.f32x2 %0, %1, %2, %3;" : "=l"(d) : "l"(a), "l"(b), "l"(c));
    return d;
}
__device__ __forceinline__ unsigned long long pack2(float lo, float hi)
{
    unsigned long long d;
    asm("mov.b64 %0, {%1, %2};" : "=l"(d) : "f"(lo), "f"(hi));
    return d;
}
__device__ __forceinline__ float2 unpack2(unsigned long long v)
{
    float2 r;
    asm("mov.b64 {%0, %1}, %2;" : "=f"(r.x), "=f"(r.y) : "l"(v));
    return r;
}
__device__ __forceinline__ unsigned int sm_u32(const void* p)
{
    return (unsigned int)__cvta_generic_to_shared(p);
}
__device__ __forceinline__ void cp16(unsigned int dst, const void* src,
                                     unsigned int bytes)
{
    asm volatile("cp.async.cg.shared.global [%0], [%1], 16, %2;"
                 :: "r"(dst), "l"(src), "r"(bytes) : "memory");
}
__device__ __forceinline__ void cp_commit()
{
    asm volatile("cp.async.commit_group;" ::: "memory");
}
template<int N>
__device__ __forceinline__ void cp_wait()
{
    asm volatile("cp.async.wait_group %0;" :: "n"(N) : "memory");
}
__device__ __forceinline__ void ldsm4(unsigned int* r, unsigned int addr)
{
    asm volatile("ldmatrix.sync.aligned.m8n8.x4.shared.b16 {%0,%1,%2,%3}, [%4];"
                 : "=r"(r[0]), "=r"(r[1]), "=r"(r[2]), "=r"(r[3]) : "r"(addr));
}
__device__ __forceinline__ void mma16816(float* c, const unsigned int* a,
                                         const unsigned int* b)
{
    asm volatile("mma.sync.aligned.m16n8k16.row.col.f32.bf16.bf16.f32 "
                 "{%0,%1,%2,%3}, {%4,%5,%6,%7}, {%8,%9}, {%0,%1,%2,%3};"
                 : "+f"(c[0]), "+f"(c[1]), "+f"(c[2]), "+f"(c[3])
                 : "r"(a[0]), "r"(a[1]), "r"(a[2]), "r"(a[3]),
                   "r"(b[0]), "r"(b[1]));
}
__device__ __forceinline__ unsigned int sw128(unsigned int bo)
{
    return bo ^ ((bo >> 3) & 0x70);
}

// ---------------- split fp32 -> bf16 hi/lo (with channel padding) ----------------
__global__ void xsplit_k(const float* __restrict__ X, __nv_bfloat16* __restrict__ Xh,
                         __nv_bfloat16* __restrict__ Xl, long R, int CIN, int CIP)
{
    long idx = (long)blockIdx.x * 256 + threadIdx.x;
    if (idx >= R * CIP) return;
    long r = idx / CIP;
    int  c = (int)(idx - r * CIP);
    float v = (c < CIN) ? X[r * CIN + c] : 0.f;
    __nv_bfloat16 h = __float2bfloat16(v);
    Xh[idx] = h;
    Xl[idx] = __float2bfloat16(v - __bfloat162float(h));
}

// W[co][ci][k] fp32 -> Wh/Wl [k][co][ci_padded] bf16
__global__ void wsplit_k(const float* __restrict__ W, __nv_bfloat16* __restrict__ Wh,
                         __nv_bfloat16* __restrict__ Wl, int CIN, int CIP, int KS)
{
    int idx = blockIdx.x * 256 + threadIdx.x;
    int total = KS * 384 * CIP;
    if (idx >= total) return;
    int k   = idx / (384 * CIP);
    int rem = idx - k * 384 * CIP;
    int co  = rem / CIP;
    int ci  = rem - co * CIP;
    float v = (ci < CIN) ? W[((size_t)co * CIN + ci) * KS + k] : 0.f;
    __nv_bfloat16 h = __float2bfloat16(v);
    Wh[idx] = h;
    Wl[idx] = __float2bfloat16(v - __bfloat162float(h));
}

// ---------------- conv1d via mma.sync bf16 split (3-term compensation) ----------
// CTA: 128 time-rows x 128 couts. 256 thr / 8 warps, warp tile 64x32.
// K streamed as (tap, 64-ch chunk) steps; A loaded with tap shift, zfill edges.
// smem/stage: Ahi|Alo|Bhi|Blo 16KB each (128 rows x 128B, SW128), 2 stages.
#define CONV_SMEM (1024 + 2 * 65536)
template<int KS, int CIP, bool RELU, bool SPLITOUT>
__global__ __launch_bounds__(256)
void convmma_k(const __nv_bfloat16* __restrict__ Xh, const __nv_bfloat16* __restrict__ Xl,
               const __nv_bfloat16* __restrict__ Wh, const __nv_bfloat16* __restrict__ Wl,
               const float* __restrict__ bias,
               __nv_bfloat16* __restrict__ Oh, __nv_bfloat16* __restrict__ Ol,
               float* __restrict__ Of, int T)
{
    constexpr int PAD = (KS - 1) / 2;
    constexpr int NC  = CIP / 64;
    constexpr int NS  = KS * NC;
    extern __shared__ char smem[];
    const unsigned int su = sm_u32(smem);

    const int tid  = threadIdx.x;
    const int lane = tid & 31;
    const int wid  = tid >> 5;
    const int wm   = wid & 1;       // 2 warp rows  (M 64 each)
    const int wn   = wid >> 1;      // 4 warp cols  (N 32 each)
    const int b    = blockIdx.z;
    const int t0   = blockIdx.x * 128;
    const int n0   = blockIdx.y * 128;

    float* sBias = (float*)smem;
    if (tid < 128) sBias[tid] = bias[n0 + tid];

    // ldmatrix per-thread address components
    const int g  = lane >> 3, wi = lane & 7;
    const int arow = ((g & 1) << 3) + wi, acg = g >> 1;       // A: a0..a3 order
    const int brow = ((g >> 1) << 3) + wi, bcg = g & 1;       // B: n16 x k16 order

    auto fill = [&](int step) {
        int s  = step & 1;
        int k  = step / NC;
        int ch = step - k * NC;
        unsigned int ah = su + 1024 + s * 65536;
        unsigned int al = ah + 16384, bh = ah + 32768, bl = ah + 49152;
        #pragma unroll
        for (int i = tid; i < 1024; i += 256) {
            int r = i >> 3, c = i & 7;
            unsigned int sw = sw128(r * 128 + c * 16);
            int t  = t0 + r + k - PAD;
            int tc = t < 0 ? 0 : (t >= T ? T - 1 : t);
            unsigned int ok = (t >= 0 && t < T) ? 16u : 0u;
            size_t src = ((size_t)b * T + tc) * CIP + ch * 64 + c * 8;
            cp16(ah + sw, Xh + src, ok);
            cp16(al + sw, Xl + src, ok);
            size_t wsrc = ((size_t)k * 384 + n0 + r) * CIP + ch * 64 + c * 8;
            cp16(bh + sw, Wh + wsrc, 16u);
            cp16(bl + sw, Wl + wsrc, 16u);
        }
        cp_commit();
    };

    float acc[4][4][4];
    #pragma unroll
    for (int i = 0; i < 4; i++)
        #pragma unroll
        for (int j = 0; j < 4; j++)
            #pragma unroll
            for (int e = 0; e < 4; e++) acc[i][j][e] = 0.f;

    fill(0);
    for (int step = 0; step < NS; step++) {
        int s = step & 1;
        if (step + 1 < NS) { fill(step + 1); cp_wait<1>(); }
        else               { cp_wait<0>(); }
        __syncthreads();

        unsigned int ab = su + 1024 + s * 65536;
        unsigned int albase = ab + 16384, bhbase = ab + 32768, blbase = ab + 49152;

        #pragma unroll
        for (int kq = 0; kq < 4; kq++) {
            unsigned int a_h[4][4], a_l[4][4], b_h[2][4], b_l[2][4];
            #pragma unroll
            for (int i = 0; i < 4; i++) {
                unsigned int bo = sw128((wm * 64 + i * 16 + arow) * 128
                                        + (kq * 2 + acg) * 16);
                ldsm4(a_h[i], ab + bo);
                ldsm4(a_l[i], albase + bo);
            }
            #pragma unroll
            for (int p = 0; p < 2; p++) {
                unsigned int bo = sw128((wn * 32 + p * 16 + brow) * 128
                                        + (kq * 2 + bcg) * 16);
                ldsm4(b_h[p], bhbase + bo);
                ldsm4(b_l[p], blbase + bo);
            }
            #pragma unroll
            for (int i = 0; i < 4; i++)
                #pragma unroll
                for (int j = 0; j < 4; j++) {
                    const unsigned int* bh2 = &b_h[j >> 1][(j & 1) * 2];
                    const unsigned int* bl2 = &b_l[j >> 1][(j & 1) * 2];
                    mma16816(acc[i][j], a_h[i], bh2);   // hi*hi
                    mma16816(acc[i][j], a_h[i], bl2);   // hi*lo
                    mma16816(acc[i][j], a_l[i], bh2);   // lo*hi
                }
        }
        __syncthreads();
    }

    // epilogue: accum layout of m16n8: rows (lane>>2)+{0,8}, cols (lane&3)*2+{0,1}
    #pragma unroll
    for (int i = 0; i < 4; i++) {
        #pragma unroll
        for (int half = 0; half < 2; half++) {
            int t = t0 + wm * 64 + i * 16 + (lane >> 2) + half * 8;
            if (t >= T) continue;
            size_t base = ((size_t)b * T + t) * 384 + n0;
            #pragma unroll
            for (int j = 0; j < 4; j++) {
                int c = wn * 32 + j * 8 + (lane & 3) * 2;
                float v0 = acc[i][j][half * 2]     + sBias[c];
                float v1 = acc[i][j][half * 2 + 1] + sBias[c + 1];
                if (RELU) { v0 = fmaxf(v0, 0.f); v1 = fmaxf(v1, 0.f); }
                if (SPLITOUT) {
                    __nv_bfloat16 h0 = __float2bfloat16(v0);
                    __nv_bfloat16 h1 = __float2bfloat16(v1);
                    __nv_bfloat162 hp; hp.x = h0; hp.y = h1;
                    __nv_bfloat162 lp;
                    lp.x = __float2bfloat16(v0 - __bfloat162float(h0));
                    lp.y = __float2bfloat16(v1 - __bfloat162float(h1));
                    *(__nv_bfloat162*)&Oh[base + c] = hp;
                    *(__nv_bfloat162*)&Ol[base + c] = lp;
                } else {
                    *(float2*)&Of[base + c] = make_float2(v0, v1);
                }
            }
        }
    }
}

// ---------------- row squared-norms over 384 features ----------------
__global__ void rownorm_k(const float* __restrict__ X, float* __restrict__ Nrm)
{
    int row = blockIdx.x;
    const float* p = X + (size_t)row * 384;
    float s = 0.f;
    for (int i = threadIdx.x; i < 384; i += 128) { float v = p[i]; s += v * v; }
    #pragma unroll
    for (int o = 16; o > 0; o >>= 1) s += __shfl_xor_sync(0xffffffffu, s, o);
    __shared__ float ps[4];
    if ((threadIdx.x & 31) == 0) ps[threadIdx.x >> 5] = s;
    __syncthreads();
    if (threadIdx.x == 0) Nrm[row] = ps[0] + ps[1] + ps[2] + ps[3];
}

// ---------------- fused distance GEMM + sqrt + mask + log_softmax ----------------
__global__ __launch_bounds__(256)
void attn_k(const float* __restrict__ Y, const float* __restrict__ H,
            const float* __restrict__ Yn, const float* __restrict__ Hn,
            const unsigned char* __restrict__ mask, float* __restrict__ Out)
{
    constexpr int CK = 8;
    constexpr int NC = ADIM / CK;
    const int b  = blockIdx.y;
    const int m0 = blockIdx.x * 64;
    const int tx = threadIdx.x, ty = threadIdx.y;
    const int tid = ty * 16 + tx;

    __shared__ unsigned long long Hs[2][192][9];
    __shared__ float HsL[2][16][9];
    __shared__ float Ysm[2][64][12];
    __shared__ float sHn[400];
    __shared__ unsigned char sM[400];

    const float* Hb = H + (size_t)b * TTEXT * ADIM;
    const float* Yb = Y + ((size_t)b * TMEL + m0) * ADIM;

    for (int i = tid; i < 400; i += 256) {
        sHn[i] = Hn[b * TTEXT + i];
        sM[i]  = mask[b * TTEXT + i];
    }

    float4 hA1, hB1, hA2, hB2, hL, yS;

    auto load_regs = [&](int ch) {
        int kc = ch * CK;
        {
            int p = tid >> 1, c4 = (tid & 1) * 4;
            hA1 = *(const float4*)&Hb[(size_t)(2 * p)     * ADIM + kc + c4];
            hB1 = *(const float4*)&Hb[(size_t)(2 * p + 1) * ADIM + kc + c4];
        }
        if (tid < 128) {
            int t2 = 256 + tid;
            int p = t2 >> 1, c4 = (t2 & 1) * 4;
            hA2 = *(const float4*)&Hb[(size_t)(2 * p)     * ADIM + kc + c4];
            hB2 = *(const float4*)&Hb[(size_t)(2 * p + 1) * ADIM + kc + c4];
        }
        if (tid < 32) {
            int l = tid >> 1, c4 = (tid & 1) * 4;
            hL = *(const float4*)&Hb[(size_t)(384 + l) * ADIM + kc + c4];
        }
        if (tid >= 128) {
            int i = tid - 128;
            int r = i >> 1, c4 = (i & 1) * 4;
            yS = *(const float4*)&Yb[(size_t)r * ADIM + kc + c4];
        }
    };
    auto store_smem = [&](int buf) {
        {
            int p = tid >> 1, c4 = (tid & 1) * 4;
            Hs[buf][p][c4 + 0] = pack2(hA1.x, hB1.x);
            Hs[buf][p][c4 + 1] = pack2(hA1.y, hB1.y);
            Hs[buf][p][c4 + 2] = pack2(hA1.z, hB1.z);
            Hs[buf][p][c4 + 3] = pack2(hA1.w, hB1.w);
        }
        if (tid < 128) {
            int t2 = 256 + tid;
            int p = t2 >> 1, c4 = (t2 & 1) * 4;
            Hs[buf][p][c4 + 0] = pack2(hA2.x, hB2.x);
            Hs[buf][p][c4 + 1] = pack2(hA2.y, hB2.y);
            Hs[buf][p][c4 + 2] = pack2(hA2.z, hB2.z);
            Hs[buf][p][c4 + 3] = pack2(hA2.w, hB2.w);
        }
        if (tid < 32) {
            int l = tid >> 1, c4 = (tid & 1) * 4;
            HsL[buf][l][c4 + 0] = hL.x; HsL[buf][l][c4 + 1] = hL.y;
            HsL[buf][l][c4 + 2] = hL.z; HsL[buf][l][c4 + 3] = hL.w;
        }
        if (tid >= 128) {
            int i = tid - 128;
            int r = i >> 1, c4 = (i & 1) * 4;
            *(float4*)&Ysm[buf][r][c4] = yS;
        }
    };

    unsigned long long s2[4][12];
    float s1[4];
    #pragma unroll
    for (int r = 0; r < 4; r++) {
        s1[r] = 0.f;
        #pragma unroll
        for (int j = 0; j < 12; j++) s2[r][j] = 0ull;
    }

    load_regs(0);
    for (int ch = 0; ch < NC; ch++) {
        int buf = ch & 1;
        store_smem(buf);
        __syncthreads();
        if (ch + 1 < NC) load_regs(ch + 1);

        #pragma unroll
        for (int kk = 0; kk < CK; kk++) {
            float yv[4];
            unsigned long long yd[4];
            #pragma unroll
            for (int r = 0; r < 4; r++) {
                yv[r] = Ysm[buf][ty * 4 + r][kk];
                yd[r] = pack2(yv[r], yv[r]);
            }
            #pragma unroll
            for (int j = 0; j < 12; j++) {
                unsigned long long hp = Hs[buf][tx + 16 * j][kk];
                #pragma unroll
                for (int r = 0; r < 4; r++) s2[r][j] = ffma2(yd[r], hp, s2[r][j]);
            }
            float hl = HsL[buf][tx][kk];
            #pragma unroll
            for (int r = 0; r < 4; r++) s1[r] += yv[r] * hl;
        }
        __syncthreads();
    }

    #pragma unroll
    for (int r = 0; r < 4; r++) {
        float s[25];
        #pragma unroll
        for (int j = 0; j < 12; j++) {
            float2 p = unpack2(s2[r][j]);
            s[2 * j]     = p.x;
            s[2 * j + 1] = p.y;
        }
        s[24] = s1[r];

        int m = m0 + ty * 4 + r;
        float yn = Yn[b * TMEL + m];
        float mx = -INFINITY;
        #pragma unroll
        for (int j = 0; j < 25; j++) {
            int t = (j < 24) ? (2 * (tx + 16 * (j >> 1)) + (j & 1)) : (384 + tx);
            float sq = yn + sHn[t] - 2.f * s[j];
            float dd = sqrtf(fmaxf(sq, 1e-12f));
            float sc = sM[t] ? -INFINITY : -dd;
            s[j] = sc;
            mx = fmaxf(mx, sc);
        }
        #pragma unroll
        for (int o = 8; o > 0; o >>= 1)
            mx = fmaxf(mx, __shfl_xor_sync(0xffffffffu, mx, o, 16));
        float sum = 0.f;
        #pragma unroll
        for (int j = 0; j < 25; j++) sum += __expf(s[j] - mx);
        #pragma unroll
        for (int o = 8; o > 0; o >>= 1)
            sum += __shfl_xor_sync(0xffffffffu, sum, o, 16);
        float lse = mx + __logf(sum);
        float* op = Out + ((size_t)b * TMEL + m) * TTEXT;
        #pragma unroll
        for (int j = 0; j < 12; j++) {
            float2 v = make_float2(s[2 * j] - lse, s[2 * j + 1] - lse);
            *(float2*)&op[2 * (tx + 16 * j)] = v;
        }
        op[384 + tx] = s[24] - lse;
    }
}

// ---------------- launch ----------------
extern "C" void kernel_launch(void* const* d_in, const int* in_sizes, int n_in,
                              void* d_out, int out_size)
{
    const float* hs   = (const float*)d_in[0];
    const float* ys   = (const float*)d_in[1];
    const unsigned char* mask = (const unsigned char*)d_in[2];
    const float* t_w1 = (const float*)d_in[3];
    const float* t_b1 = (const float*)d_in[4];
    const float* t_w2 = (const float*)d_in[5];
    const float* t_b2 = (const float*)d_in[6];
    const float* m_w1 = (const float*)d_in[7];
    const float* m_b1 = (const float*)d_in[8];
    const float* m_w2 = (const float*)d_in[9];
    const float* m_b2 = (const float*)d_in[10];
    const float* m_w3 = (const float*)d_in[11];
    const float* m_b3 = (const float*)d_in[12];
    float* out = (float*)d_out;

    __nv_bfloat16 *xht, *xlt, *h1h, *h1l, *xhm, *xlm, *y1h, *y1l, *y2h, *y2l;
    __nv_bfloat16 *wt1h, *wt1l, *wt2h, *wt2l, *wm1h, *wm1l, *wm2h, *wm2l, *wm3h, *wm3l;
    float *h2, *y1f, *hn, *yn;
    cudaGetSymbolAddress((void**)&xht, g_xht); cudaGetSymbolAddress((void**)&xlt, g_xlt);
    cudaGetSymbolAddress((void**)&h1h, g_h1h); cudaGetSymbolAddress((void**)&h1l, g_h1l);
    cudaGetSymbolAddress((void**)&xhm, g_xhm); cudaGetSymbolAddress((void**)&xlm, g_xlm);
    cudaGetSymbolAddress((void**)&y1h, g_y1h); cudaGetSymbolAddress((void**)&y1l, g_y1l);
    cudaGetSymbolAddress((void**)&y2h, g_y2h); cudaGetSymbolAddress((void**)&y2l, g_y2l);
    cudaGetSymbolAddress((void**)&wt1h, g_wt1h); cudaGetSymbolAddress((void**)&wt1l, g_wt1l);
    cudaGetSymbolAddress((void**)&wt2h, g_wt2h); cudaGetSymbolAddress((void**)&wt2l, g_wt2l);
    cudaGetSymbolAddress((void**)&wm1h, g_wm1h); cudaGetSymbolAddress((void**)&wm1l, g_wm1l);
    cudaGetSymbolAddress((void**)&wm2h, g_wm2h); cudaGetSymbolAddress((void**)&wm2l, g_wm2l);
    cudaGetSymbolAddress((void**)&wm3h, g_wm3h); cudaGetSymbolAddress((void**)&wm3l, g_wm3l);
    cudaGetSymbolAddress((void**)&h2, g_h2);   cudaGetSymbolAddress((void**)&y1f, g_y1);
    cudaGetSymbolAddress((void**)&hn, g_hn);   cudaGetSymbolAddress((void**)&yn, g_yn);

    cudaFuncSetAttribute(convmma_k<3, 384, true,  true >,
                         cudaFuncAttributeMaxDynamicSharedMemorySize, CONV_SMEM);
    cudaFuncSetAttribute(convmma_k<1, 384, false, false>,
                         cudaFuncAttributeMaxDynamicSharedMemorySize, CONV_SMEM);
    cudaFuncSetAttribute(convmma_k<3, 128, true,  true >,
                         cudaFuncAttributeMaxDynamicSharedMemorySize, CONV_SMEM);

    // input + weight splits
    {
        long Rt = (long)BB * TTEXT, Rm = (long)BB * TMEL;
        xsplit_k<<<(unsigned)((Rt * ADIM + 255) / 256), 256>>>(hs, xht, xlt, Rt, ADIM, ADIM);
        xsplit_k<<<(unsigned)((Rm * CIPM + 255) / 256), 256>>>(ys, xhm, xlm, Rm, ODIM, CIPM);
        wsplit_k<<<(3 * 384 * ADIM + 255) / 256, 256>>>(t_w1, wt1h, wt1l, ADIM, ADIM, 3);
        wsplit_k<<<(1 * 384 * ADIM + 255) / 256, 256>>>(t_w2, wt2h, wt2l, ADIM, ADIM, 1);
        wsplit_k<<<(3 * 384 * CIPM + 255) / 256, 256>>>(m_w1, wm1h, wm1l, ODIM, CIPM, 3);
        wsplit_k<<<(3 * 384 * ADIM + 255) / 256, 256>>>(m_w2, wm2h, wm2l, ADIM, ADIM, 3);
        wsplit_k<<<(1 * 384 * ADIM + 255) / 256, 256>>>(m_w3, wm3h, wm3l, ADIM, ADIM, 1);
    }

    // text prenet
    {
        dim3 g((TTEXT + 127) / 128, 3, BB);
        convmma_k<3, 384, true,  true ><<<g, 256, CONV_SMEM>>>(
            xht, xlt, wt1h, wt1l, t_b1, h1h, h1l, nullptr, TTEXT);
        convmma_k<1, 384, false, false><<<g, 256, CONV_SMEM>>>(
            h1h, h1l, wt2h, wt2l, t_b2, nullptr, nullptr, h2, TTEXT);
    }
    // mel prenet
    {
        dim3 g((TMEL + 127) / 128, 3, BB);
        convmma_k<3, 128, true,  true ><<<g, 256, CONV_SMEM>>>(
            xhm, xlm, wm1h, wm1l, m_b1, y1h, y1l, nullptr, TMEL);
        convmma_k<3, 384, true,  true ><<<g, 256, CONV_SMEM>>>(
            y1h, y1l, wm2h, wm2l, m_b2, y2h, y2l, nullptr, TMEL);
        convmma_k<1, 384, false, false><<<g, 256, CONV_SMEM>>>(
            y2h, y2l, wm3h, wm3l, m_b3, nullptr, nullptr, y1f, TMEL);
    }

    // row norms
    rownorm_k<<<BB * TTEXT, 128>>>(h2, hn);
    rownorm_k<<<BB * TMEL, 128>>>(y1f, yn);

    // fused distance + log_softmax
    {
        dim3 blk(16, 16);
        dim3 g(TMEL / 64, BB);
        attn_k<<<g, blk>>>(y1f, h2, yn, hn, mask, out);
    }
}

// round 7
// speedup vs baseline: 4.1834x; 1.2362x over previous
#include <cuda_runtime.h>
#include <cuda_bf16.h>
#include <math.h>
#include <stdint.h>

#define BB    32
#define TTEXT 400
#define TMEL  1600
#define ADIM  384
#define ODIM  80
#define CIPM  128   // mel input channels padded 80 -> 128

// ---------------- static scratch (no allocations allowed) ----------------
__device__ __nv_bfloat16 g_xht[(size_t)BB * TTEXT * ADIM];
__device__ __nv_bfloat16 g_xlt[(size_t)BB * TTEXT * ADIM];
__device__ __nv_bfloat16 g_h1h[(size_t)BB * TTEXT * ADIM];
__device__ __nv_bfloat16 g_h1l[(size_t)BB * TTEXT * ADIM];
__device__ __nv_bfloat16 g_xhm[(size_t)BB * TMEL * CIPM];
__device__ __nv_bfloat16 g_xlm[(size_t)BB * TMEL * CIPM];
__device__ __nv_bfloat16 g_y1h[(size_t)BB * TMEL * ADIM];
__device__ __nv_bfloat16 g_y1l[(size_t)BB * TMEL * ADIM];
__device__ __nv_bfloat16 g_y2h[(size_t)BB * TMEL * ADIM];
__device__ __nv_bfloat16 g_y2l[(size_t)BB * TMEL * ADIM];
// weights bf16 hi/lo, layout [k][co][ci_padded]
__device__ __nv_bfloat16 g_wt1h[3 * 384 * ADIM], g_wt1l[3 * 384 * ADIM];
__device__ __nv_bfloat16 g_wt2h[1 * 384 * ADIM], g_wt2l[1 * 384 * ADIM];
__device__ __nv_bfloat16 g_wm1h[3 * 384 * CIPM], g_wm1l[3 * 384 * CIPM];
__device__ __nv_bfloat16 g_wm2h[3 * 384 * ADIM], g_wm2l[3 * 384 * ADIM];
__device__ __nv_bfloat16 g_wm3h[1 * 384 * ADIM], g_wm3l[1 * 384 * ADIM];
__device__ float g_hn[BB * TTEXT];
__device__ float g_yn[BB * TMEL];

// ---------------- PTX helpers (family-level only) ----------------
__device__ __forceinline__ unsigned int sm_u32(const void* p)
{
    return (unsigned int)__cvta_generic_to_shared(p);
}
__device__ __forceinline__ void cp16(unsigned int dst, const void* src,
                                     unsigned int bytes)
{
    asm volatile("cp.async.cg.shared.global [%0], [%1], 16, %2;"
                 :: "r"(dst), "l"(src), "r"(bytes) : "memory");
}
__device__ __forceinline__ void cp_commit()
{
    asm volatile("cp.async.commit_group;" ::: "memory");
}
template<int N>
__device__ __forceinline__ void cp_wait()
{
    asm volatile("cp.async.wait_group %0;" :: "n"(N) : "memory");
}
__device__ __forceinline__ void ldsm4(unsigned int* r, unsigned int addr)
{
    asm volatile("ldmatrix.sync.aligned.m8n8.x4.shared.b16 {%0,%1,%2,%3}, [%4];"
                 : "=r"(r[0]), "=r"(r[1]), "=r"(r[2]), "=r"(r[3]) : "r"(addr));
}
__device__ __forceinline__ void mma16816(float* c, const unsigned int* a,
                                         const unsigned int* b)
{
    asm volatile("mma.sync.aligned.m16n8k16.row.col.f32.bf16.bf16.f32 "
                 "{%0,%1,%2,%3}, {%4,%5,%6,%7}, {%8,%9}, {%0,%1,%2,%3};"
                 : "+f"(c[0]), "+f"(c[1]), "+f"(c[2]), "+f"(c[3])
                 : "r"(a[0]), "r"(a[1]), "r"(a[2]), "r"(a[3]),
                   "r"(b[0]), "r"(b[1]));
}
__device__ __forceinline__ unsigned int sw128(unsigned int bo)
{
    return bo ^ ((bo >> 3) & 0x70);
}

// ---------------- split fp32 -> bf16 hi/lo (with channel padding) ----------------
__global__ void xsplit_k(const float* __restrict__ X, __nv_bfloat16* __restrict__ Xh,
                         __nv_bfloat16* __restrict__ Xl, long R, int CIN, int CIP)
{
    long idx = (long)blockIdx.x * 256 + threadIdx.x;
    if (idx >= R * CIP) return;
    long r = idx / CIP;
    int  c = (int)(idx - r * CIP);
    float v = (c < CIN) ? X[r * CIN + c] : 0.f;
    __nv_bfloat16 h = __float2bfloat16(v);
    Xh[idx] = h;
    Xl[idx] = __float2bfloat16(v - __bfloat162float(h));
}

// W[co][ci][k] fp32 -> Wh/Wl [k][co][ci_padded] bf16
__global__ void wsplit_k(const float* __restrict__ W, __nv_bfloat16* __restrict__ Wh,
                         __nv_bfloat16* __restrict__ Wl, int CIN, int CIP, int KS)
{
    int idx = blockIdx.x * 256 + threadIdx.x;
    int total = KS * 384 * CIP;
    if (idx >= total) return;
    int k   = idx / (384 * CIP);
    int rem = idx - k * 384 * CIP;
    int co  = rem / CIP;
    int ci  = rem - co * CIP;
    float v = (ci < CIN) ? W[((size_t)co * CIN + ci) * KS + k] : 0.f;
    __nv_bfloat16 h = __float2bfloat16(v);
    Wh[idx] = h;
    Wl[idx] = __float2bfloat16(v - __bfloat162float(h));
}

// ---------------- conv1d via mma.sync bf16 split (3-term compensation) ----------
#define CONV_SMEM (1024 + 2 * 65536)
template<int KS, int CIP, bool RELU>
__global__ __launch_bounds__(256)
void convmma_k(const __nv_bfloat16* __restrict__ Xh, const __nv_bfloat16* __restrict__ Xl,
               const __nv_bfloat16* __restrict__ Wh, const __nv_bfloat16* __restrict__ Wl,
               const float* __restrict__ bias,
               __nv_bfloat16* __restrict__ Oh, __nv_bfloat16* __restrict__ Ol, int T)
{
    constexpr int PAD = (KS - 1) / 2;
    constexpr int NC  = CIP / 64;
    constexpr int NS  = KS * NC;
    extern __shared__ char smem[];
    const unsigned int su = sm_u32(smem);

    const int tid  = threadIdx.x;
    const int lane = tid & 31;
    const int wid  = tid >> 5;
    const int wm   = wid & 1;
    const int wn   = wid >> 1;
    const int b    = blockIdx.z;
    const int t0   = blockIdx.x * 128;
    const int n0   = blockIdx.y * 128;

    float* sBias = (float*)smem;
    if (tid < 128) sBias[tid] = bias[n0 + tid];

    const int g  = lane >> 3, wi = lane & 7;
    const int arow = ((g & 1) << 3) + wi, acg = g >> 1;
    const int brow = ((g >> 1) << 3) + wi, bcg = g & 1;

    auto fill = [&](int step) {
        int s  = step & 1;
        int k  = step / NC;
        int ch = step - k * NC;
        unsigned int ah = su + 1024 + s * 65536;
        unsigned int al = ah + 16384, bh = ah + 32768, bl = ah + 49152;
        #pragma unroll
        for (int i = tid; i < 1024; i += 256) {
            int r = i >> 3, c = i & 7;
            unsigned int sw = sw128(r * 128 + c * 16);
            int t  = t0 + r + k - PAD;
            int tc = t < 0 ? 0 : (t >= T ? T - 1 : t);
            unsigned int ok = (t >= 0 && t < T) ? 16u : 0u;
            size_t src = ((size_t)b * T + tc) * CIP + ch * 64 + c * 8;
            cp16(ah + sw, Xh + src, ok);
            cp16(al + sw, Xl + src, ok);
            size_t wsrc = ((size_t)k * 384 + n0 + r) * CIP + ch * 64 + c * 8;
            cp16(bh + sw, Wh + wsrc, 16u);
            cp16(bl + sw, Wl + wsrc, 16u);
        }
        cp_commit();
    };

    float acc[4][4][4];
    #pragma unroll
    for (int i = 0; i < 4; i++)
        #pragma unroll
        for (int j = 0; j < 4; j++)
            #pragma unroll
            for (int e = 0; e < 4; e++) acc[i][j][e] = 0.f;

    fill(0);
    for (int step = 0; step < NS; step++) {
        int s = step & 1;
        if (step + 1 < NS) { fill(step + 1); cp_wait<1>(); }
        else               { cp_wait<0>(); }
        __syncthreads();

        unsigned int ab = su + 1024 + s * 65536;
        unsigned int albase = ab + 16384, bhbase = ab + 32768, blbase = ab + 49152;

        #pragma unroll
        for (int kq = 0; kq < 4; kq++) {
            unsigned int a_h[4][4], a_l[4][4], b_h[2][4], b_l[2][4];
            #pragma unroll
            for (int i = 0; i < 4; i++) {
                unsigned int bo = sw128((wm * 64 + i * 16 + arow) * 128
                                        + (kq * 2 + acg) * 16);
                ldsm4(a_h[i], ab + bo);
                ldsm4(a_l[i], albase + bo);
            }
            #pragma unroll
            for (int p = 0; p < 2; p++) {
                unsigned int bo = sw128((wn * 32 + p * 16 + brow) * 128
                                        + (kq * 2 + bcg) * 16);
                ldsm4(b_h[p], bhbase + bo);
                ldsm4(b_l[p], blbase + bo);
            }
            #pragma unroll
            for (int i = 0; i < 4; i++)
                #pragma unroll
                for (int j = 0; j < 4; j++) {
                    const unsigned int* bh2 = &b_h[j >> 1][(j & 1) * 2];
                    const unsigned int* bl2 = &b_l[j >> 1][(j & 1) * 2];
                    mma16816(acc[i][j], a_h[i], bh2);
                    mma16816(acc[i][j], a_h[i], bl2);
                    mma16816(acc[i][j], a_l[i], bh2);
                }
        }
        __syncthreads();
    }

    #pragma unroll
    for (int i = 0; i < 4; i++) {
        #pragma unroll
        for (int half = 0; half < 2; half++) {
            int t = t0 + wm * 64 + i * 16 + (lane >> 2) + half * 8;
            if (t >= T) continue;
            size_t base = ((size_t)b * T + t) * 384 + n0;
            #pragma unroll
            for (int j = 0; j < 4; j++) {
                int c = wn * 32 + j * 8 + (lane & 3) * 2;
                float v0 = acc[i][j][half * 2]     + sBias[c];
                float v1 = acc[i][j][half * 2 + 1] + sBias[c + 1];
                if (RELU) { v0 = fmaxf(v0, 0.f); v1 = fmaxf(v1, 0.f); }
                __nv_bfloat16 h0 = __float2bfloat16(v0);
                __nv_bfloat16 h1 = __float2bfloat16(v1);
                __nv_bfloat162 hp; hp.x = h0; hp.y = h1;
                __nv_bfloat162 lp;
                lp.x = __float2bfloat16(v0 - __bfloat162float(h0));
                lp.y = __float2bfloat16(v1 - __bfloat162float(h1));
                *(__nv_bfloat162*)&Oh[base + c] = hp;
                *(__nv_bfloat162*)&Ol[base + c] = lp;
            }
        }
    }
}

// ---------------- row squared-norms from hi/lo over 384 features ----------------
__global__ void rownorm2_k(const __nv_bfloat16* __restrict__ Xh,
                           const __nv_bfloat16* __restrict__ Xl,
                           float* __restrict__ Nrm)
{
    int row = blockIdx.x;
    const __nv_bfloat16* ph = Xh + (size_t)row * 384;
    const __nv_bfloat16* pl = Xl + (size_t)row * 384;
    float s = 0.f;
    for (int i = threadIdx.x; i < 384; i += 128) {
        float v = __bfloat162float(ph[i]) + __bfloat162float(pl[i]);
        s += v * v;
    }
    #pragma unroll
    for (int o = 16; o > 0; o >>= 1) s += __shfl_xor_sync(0xffffffffu, s, o);
    __shared__ float ps[4];
    if ((threadIdx.x & 31) == 0) ps[threadIdx.x >> 5] = s;
    __syncthreads();
    if (threadIdx.x == 0) Nrm[row] = ps[0] + ps[1] + ps[2] + ps[3];
}

// ---------------- fused distance mma-GEMM + sqrt + mask + log_softmax --------
// CTA: 64 mel rows x 400 text cols. 8 warps: wm=wid&3 (16 rows), wn=wid>>2 (200 cols).
// K chunks of 32, double-buffered cp.async. Fragments via plain LDS.32 from
// pitch-20-word rows (conflict-free lane permutation). 3-term bf16 split dot.
#define ATTN_STAGE 74240
#define ATTN_SMEM  (2112 + 2 * ATTN_STAGE)
__global__ __launch_bounds__(256)
void attnmma_k(const __nv_bfloat16* __restrict__ Yh, const __nv_bfloat16* __restrict__ Yl,
               const __nv_bfloat16* __restrict__ Hh, const __nv_bfloat16* __restrict__ Hl,
               const float* __restrict__ Yn, const float* __restrict__ Hn,
               const unsigned char* __restrict__ mask, float* __restrict__ Out)
{
    constexpr int NSTEP = ADIM / 32;   // 12
    extern __shared__ char smem[];
    float* sHnM = (float*)smem;                       // [400] (+inf where masked)
    float* sRed = (float*)(smem + 1600);              // [4][16][2]
    const unsigned int su = sm_u32(smem);

    const int tid  = threadIdx.x;
    const int lane = tid & 31;
    const int wid  = tid >> 5;
    const int wm   = wid & 3;       // 4 M groups of 16 rows
    const int wn   = wid >> 2;      // 2 N halves of 200 cols
    const int b    = blockIdx.y;
    const int m0   = blockIdx.x * 64;

    for (int i = tid; i < 400; i += 256)
        sHnM[i] = mask[b * TTEXT + i] ? __int_as_float(0x7f800000) : Hn[b * TTEXT + i];

    // stage layout (word units, pitch 20 words/row):
    //  Yh[64][20] @0, Yl @5120B, Hh[400][20] @10240B, Hl @42240B
    auto fill = [&](int step) {
        int s = step & 1;
        int kc = step * 32;
        unsigned int st = su + 2112 + s * ATTN_STAGE;
        #pragma unroll 2
        for (int i = tid; i < 1600; i += 256) {        // H rows
            int n = i >> 2, q = i & 3;
            unsigned int dst = st + 10240 + (n * 20 + q * 4) * 4;
            size_t src = ((size_t)b * TTEXT + n) * ADIM + kc + q * 8;
            cp16(dst,         Hh + src, 16u);
            cp16(dst + 32000, Hl + src, 16u);
        }
        {
            int i = tid;                                // Y rows (256 tasks)
            int r = i >> 2, q = i & 3;
            unsigned int dst = st + (r * 20 + q * 4) * 4;
            size_t src = ((size_t)b * TMEL + m0 + r) * ADIM + kc + q * 8;
            cp16(dst,        Yh + src, 16u);
            cp16(dst + 5120, Yl + src, 16u);
        }
        cp_commit();
    };

    float acc[25][4];
    #pragma unroll
    for (int j = 0; j < 25; j++)
        #pragma unroll
        for (int e = 0; e < 4; e++) acc[j][e] = 0.f;

    const int r0 = lane >> 2;        // fragment row within 16
    const int lw = lane & 3;         // fragment k-word lane

    fill(0);
    for (int step = 0; step < NSTEP; step++) {
        int s = step & 1;
        if (step + 1 < NSTEP) { fill(step + 1); cp_wait<1>(); }
        else                  { cp_wait<0>(); }
        __syncthreads();

        const unsigned int st = su + 2112 + s * ATTN_STAGE;
        const uint32_t* Ys_h = (const uint32_t*)(smem + (st - su));
        const uint32_t* Ys_l = Ys_h + 1280;            // 5120B
        const uint32_t* Hs_h = Ys_h + 2560;            // 10240B
        const uint32_t* Hs_l = Hs_h + 8000;            // 32000B

        #pragma unroll
        for (int kq = 0; kq < 2; kq++) {
            const int w0 = kq * 8 + lw;
            unsigned int ah[4], al[4];
            {
                int ra = (wm * 16 + r0) * 20;
                int rb = (wm * 16 + r0 + 8) * 20;
                ah[0] = Ys_h[ra + w0];     ah[1] = Ys_h[rb + w0];
                ah[2] = Ys_h[ra + w0 + 4]; ah[3] = Ys_h[rb + w0 + 4];
                al[0] = Ys_l[ra + w0];     al[1] = Ys_l[rb + w0];
                al[2] = Ys_l[ra + w0 + 4]; al[3] = Ys_l[rb + w0 + 4];
            }
            #pragma unroll
            for (int j = 0; j < 25; j++) {
                int n = (wn * 200 + j * 8 + r0) * 20;
                unsigned int bh[2], bl[2];
                bh[0] = Hs_h[n + w0]; bh[1] = Hs_h[n + w0 + 4];
                bl[0] = Hs_l[n + w0]; bl[1] = Hs_l[n + w0 + 4];
                mma16816(acc[j], ah, bh);
                mma16816(acc[j], ah, bl);
                mma16816(acc[j], al, bh);
            }
        }
        __syncthreads();
    }

    // ---- epilogue: scores + log_softmax ----
    int mrow0 = m0 + wm * 16 + r0;
    float yn0 = Yn[b * TMEL + mrow0];
    float yn1 = Yn[b * TMEL + mrow0 + 8];

    #pragma unroll
    for (int j = 0; j < 25; j++) {
        int c = wn * 200 + j * 8 + lw * 2;
        float hn0 = sHnM[c], hn1 = sHnM[c + 1];
        acc[j][0] = -sqrtf(fmaxf(yn0 + hn0 - 2.f * acc[j][0], 1e-12f));
        acc[j][1] = -sqrtf(fmaxf(yn0 + hn1 - 2.f * acc[j][1], 1e-12f));
        acc[j][2] = -sqrtf(fmaxf(yn1 + hn0 - 2.f * acc[j][2], 1e-12f));
        acc[j][3] = -sqrtf(fmaxf(yn1 + hn1 - 2.f * acc[j][3], 1e-12f));
    }

    float mx0 = -INFINITY, mx1 = -INFINITY;
    #pragma unroll
    for (int j = 0; j < 25; j++) {
        mx0 = fmaxf(mx0, fmaxf(acc[j][0], acc[j][1]));
        mx1 = fmaxf(mx1, fmaxf(acc[j][2], acc[j][3]));
    }
    #pragma unroll
    for (int o = 1; o <= 2; o <<= 1) {
        mx0 = fmaxf(mx0, __shfl_xor_sync(0xffffffffu, mx0, o));
        mx1 = fmaxf(mx1, __shfl_xor_sync(0xffffffffu, mx1, o));
    }
    if (lw == 0) {
        sRed[(wm * 16 + r0) * 2 + wn]     = mx0;
        sRed[(wm * 16 + r0 + 8) * 2 + wn] = mx1;
    }
    __syncthreads();
    mx0 = fmaxf(sRed[(wm * 16 + r0) * 2],     sRed[(wm * 16 + r0) * 2 + 1]);
    mx1 = fmaxf(sRed[(wm * 16 + r0 + 8) * 2], sRed[(wm * 16 + r0 + 8) * 2 + 1]);
    __syncthreads();

    float sm0 = 0.f, sm1 = 0.f;
    #pragma unroll
    for (int j = 0; j < 25; j++) {
        sm0 += __expf(acc[j][0] - mx0) + __expf(acc[j][1] - mx0);
        sm1 += __expf(acc[j][2] - mx1) + __expf(acc[j][3] - mx1);
    }
    #pragma unroll
    for (int o = 1; o <= 2; o <<= 1) {
        sm0 += __shfl_xor_sync(0xffffffffu, sm0, o);
        sm1 += __shfl_xor_sync(0xffffffffu, sm1, o);
    }
    if (lw == 0) {
        sRed[(wm * 16 + r0) * 2 + wn]     = sm0;
        sRed[(wm * 16 + r0 + 8) * 2 + wn] = sm1;
    }
    __syncthreads();
    sm0 = sRed[(wm * 16 + r0) * 2]     + sRed[(wm * 16 + r0) * 2 + 1];
    sm1 = sRed[(wm * 16 + r0 + 8) * 2] + sRed[(wm * 16 + r0 + 8) * 2 + 1];
    float lse0 = mx0 + __logf(sm0);
    float lse1 = mx1 + __logf(sm1);

    float* o0 = Out + ((size_t)b * TMEL + mrow0) * TTEXT;
    float* o1 = Out + ((size_t)b * TMEL + mrow0 + 8) * TTEXT;
    #pragma unroll
    for (int j = 0; j < 25; j++) {
        int c = wn * 200 + j * 8 + lw * 2;
        *(float2*)&o0[c] = make_float2(acc[j][0] - lse0, acc[j][1] - lse0);
        *(float2*)&o1[c] = make_float2(acc[j][2] - lse1, acc[j][3] - lse1);
    }
}

// ---------------- launch ----------------
extern "C" void kernel_launch(void* const* d_in, const int* in_sizes, int n_in,
                              void* d_out, int out_size)
{
    const float* hs   = (const float*)d_in[0];
    const float* ys   = (const float*)d_in[1];
    const unsigned char* mask = (const unsigned char*)d_in[2];
    const float* t_w1 = (const float*)d_in[3];
    const float* t_b1 = (const float*)d_in[4];
    const float* t_w2 = (const float*)d_in[5];
    const float* t_b2 = (const float*)d_in[6];
    const float* m_w1 = (const float*)d_in[7];
    const float* m_b1 = (const float*)d_in[8];
    const float* m_w2 = (const float*)d_in[9];
    const float* m_b2 = (const float*)d_in[10];
    const float* m_w3 = (const float*)d_in[11];
    const float* m_b3 = (const float*)d_in[12];
    float* out = (float*)d_out;

    __nv_bfloat16 *xht, *xlt, *h1h, *h1l, *xhm, *xlm, *y1h, *y1l, *y2h, *y2l;
    __nv_bfloat16 *wt1h, *wt1l, *wt2h, *wt2l, *wm1h, *wm1l, *wm2h, *wm2l, *wm3h, *wm3l;
    float *hn, *yn;
    cudaGetSymbolAddress((void**)&xht, g_xht); cudaGetSymbolAddress((void**)&xlt, g_xlt);
    cudaGetSymbolAddress((void**)&h1h, g_h1h); cudaGetSymbolAddress((void**)&h1l, g_h1l);
    cudaGetSymbolAddress((void**)&xhm, g_xhm); cudaGetSymbolAddress((void**)&xlm, g_xlm);
    cudaGetSymbolAddress((void**)&y1h, g_y1h); cudaGetSymbolAddress((void**)&y1l, g_y1l);
    cudaGetSymbolAddress((void**)&y2h, g_y2h); cudaGetSymbolAddress((void**)&y2l, g_y2l);
    cudaGetSymbolAddress((void**)&wt1h, g_wt1h); cudaGetSymbolAddress((void**)&wt1l, g_wt1l);
    cudaGetSymbolAddress((void**)&wt2h, g_wt2h); cudaGetSymbolAddress((void**)&wt2l, g_wt2l);
    cudaGetSymbolAddress((void**)&wm1h, g_wm1h); cudaGetSymbolAddress((void**)&wm1l, g_wm1l);
    cudaGetSymbolAddress((void**)&wm2h, g_wm2h); cudaGetSymbolAddress((void**)&wm2l, g_wm2l);
    cudaGetSymbolAddress((void**)&wm3h, g_wm3h); cudaGetSymbolAddress((void**)&wm3l, g_wm3l);
    cudaGetSymbolAddress((void**)&hn, g_hn);   cudaGetSymbolAddress((void**)&yn, g_yn);

    cudaFuncSetAttribute(convmma_k<3, 384, true >,
                         cudaFuncAttributeMaxDynamicSharedMemorySize, CONV_SMEM);
    cudaFuncSetAttribute(convmma_k<1, 384, false>,
                         cudaFuncAttributeMaxDynamicSharedMemorySize, CONV_SMEM);
    cudaFuncSetAttribute(convmma_k<3, 128, true >,
                         cudaFuncAttributeMaxDynamicSharedMemorySize, CONV_SMEM);
    cudaFuncSetAttribute(attnmma_k,
                         cudaFuncAttributeMaxDynamicSharedMemorySize, ATTN_SMEM);

    // input + weight splits
    {
        long Rt = (long)BB * TTEXT, Rm = (long)BB * TMEL;
        xsplit_k<<<(unsigned)((Rt * ADIM + 255) / 256), 256>>>(hs, xht, xlt, Rt, ADIM, ADIM);
        xsplit_k<<<(unsigned)((Rm * CIPM + 255) / 256), 256>>>(ys, xhm, xlm, Rm, ODIM, CIPM);
        wsplit_k<<<(3 * 384 * ADIM + 255) / 256, 256>>>(t_w1, wt1h, wt1l, ADIM, ADIM, 3);
        wsplit_k<<<(1 * 384 * ADIM + 255) / 256, 256>>>(t_w2, wt2h, wt2l, ADIM, ADIM, 1);
        wsplit_k<<<(3 * 384 * CIPM + 255) / 256, 256>>>(m_w1, wm1h, wm1l, ODIM, CIPM, 3);
        wsplit_k<<<(3 * 384 * ADIM + 255) / 256, 256>>>(m_w2, wm2h, wm2l, ADIM, ADIM, 3);
        wsplit_k<<<(1 * 384 * ADIM + 255) / 256, 256>>>(m_w3, wm3h, wm3l, ADIM, ADIM, 1);
    }

    // text prenet: conv1 xht->h1 ; conv2 h1->xht (reuse, no aliasing)
    {
        dim3 g((TTEXT + 127) / 128, 3, BB);
        convmma_k<3, 384, true ><<<g, 256, CONV_SMEM>>>(
            xht, xlt, wt1h, wt1l, t_b1, h1h, h1l, TTEXT);
        convmma_k<1, 384, false><<<g, 256, CONV_SMEM>>>(
            h1h, h1l, wt2h, wt2l, t_b2, xht, xlt, TTEXT);
    }
    // mel prenet: conv1 xhm->y1 ; conv2 y1->y2 ; conv3 y2->y1 (reuse)
    {
        dim3 g((TMEL + 127) / 128, 3, BB);
        convmma_k<3, 128, true ><<<g, 256, CONV_SMEM>>>(
            xhm, xlm, wm1h, wm1l, m_b1, y1h, y1l, TMEL);
        convmma_k<3, 384, true ><<<g, 256, CONV_SMEM>>>(
            y1h, y1l, wm2h, wm2l, m_b2, y2h, y2l, TMEL);
        convmma_k<1, 384, false><<<g, 256, CONV_SMEM>>>(
            y2h, y2l, wm3h, wm3l, m_b3, y1h, y1l, TMEL);
    }

    // row norms from hi/lo
    rownorm2_k<<<BB * TTEXT, 128>>>(xht, xlt, hn);
    rownorm2_k<<<BB * TMEL, 128>>>(y1h, y1l, yn);

    // fused distance + log_softmax (tensor-core)
    {
        dim3 g(TMEL / 64, BB);
        attnmma_k<<<g, 256, ATTN_SMEM>>>(y1h, y1l, xht, xlt, yn, hn, mask, out);
    }
}

// round 8
// speedup vs baseline: 4.3682x; 1.0442x over previous
#include <cuda_runtime.h>
#include <cuda_bf16.h>
#include <math.h>
#include <stdint.h>

#define BB    32
#define TTEXT 400
#define TMEL  1600
#define ADIM  384
#define ODIM  80
#define CIPM  128   // mel input channels padded 80 -> 128

// ---------------- static scratch (no allocations allowed) ----------------
__device__ __nv_bfloat16 g_xht[(size_t)BB * TTEXT * ADIM];
__device__ __nv_bfloat16 g_xlt[(size_t)BB * TTEXT * ADIM];
__device__ __nv_bfloat16 g_h1h[(size_t)BB * TTEXT * ADIM];
__device__ __nv_bfloat16 g_h1l[(size_t)BB * TTEXT * ADIM];
__device__ __nv_bfloat16 g_xhm[(size_t)BB * TMEL * CIPM];
__device__ __nv_bfloat16 g_xlm[(size_t)BB * TMEL * CIPM];
__device__ __nv_bfloat16 g_y1h[(size_t)BB * TMEL * ADIM];
__device__ __nv_bfloat16 g_y1l[(size_t)BB * TMEL * ADIM];
__device__ __nv_bfloat16 g_y2h[(size_t)BB * TMEL * ADIM];
__device__ __nv_bfloat16 g_y2l[(size_t)BB * TMEL * ADIM];
// weights bf16 hi/lo, layout [k][co][ci_padded]
__device__ __nv_bfloat16 g_wt1h[3 * 384 * ADIM], g_wt1l[3 * 384 * ADIM];
__device__ __nv_bfloat16 g_wt2h[1 * 384 * ADIM], g_wt2l[1 * 384 * ADIM];
__device__ __nv_bfloat16 g_wm1h[3 * 384 * CIPM], g_wm1l[3 * 384 * CIPM];
__device__ __nv_bfloat16 g_wm2h[3 * 384 * ADIM], g_wm2l[3 * 384 * ADIM];
__device__ __nv_bfloat16 g_wm3h[1 * 384 * ADIM], g_wm3l[1 * 384 * ADIM];
__device__ float g_hn[BB * TTEXT];
__device__ float g_yn[BB * TMEL];

// ---------------- PTX helpers (family-level only) ----------------
__device__ __forceinline__ unsigned int sm_u32(const void* p)
{
    return (unsigned int)__cvta_generic_to_shared(p);
}
__device__ __forceinline__ void cp16(unsigned int dst, const void* src,
                                     unsigned int bytes)
{
    asm volatile("cp.async.cg.shared.global [%0], [%1], 16, %2;"
                 :: "r"(dst), "l"(src), "r"(bytes) : "memory");
}
__device__ __forceinline__ void cp_commit()
{
    asm volatile("cp.async.commit_group;" ::: "memory");
}
template<int N>
__device__ __forceinline__ void cp_wait()
{
    asm volatile("cp.async.wait_group %0;" :: "n"(N) : "memory");
}
__device__ __forceinline__ void ldsm4(unsigned int* r, unsigned int addr)
{
    asm volatile("ldmatrix.sync.aligned.m8n8.x4.shared.b16 {%0,%1,%2,%3}, [%4];"
                 : "=r"(r[0]), "=r"(r[1]), "=r"(r[2]), "=r"(r[3]) : "r"(addr));
}
__device__ __forceinline__ void mma16816(float* c, const unsigned int* a,
                                         const unsigned int* b)
{
    asm volatile("mma.sync.aligned.m16n8k16.row.col.f32.bf16.bf16.f32 "
                 "{%0,%1,%2,%3}, {%4,%5,%6,%7}, {%8,%9}, {%0,%1,%2,%3};"
                 : "+f"(c[0]), "+f"(c[1]), "+f"(c[2]), "+f"(c[3])
                 : "r"(a[0]), "r"(a[1]), "r"(a[2]), "r"(a[3]),
                   "r"(b[0]), "r"(b[1]));
}
__device__ __forceinline__ unsigned int sw128(unsigned int bo)
{
    return bo ^ ((bo >> 3) & 0x70);
}

// ---------------- merged input split: text + mel in one launch ----------------
__global__ void xsplit_all_k(const float* __restrict__ hs, const float* __restrict__ ys,
                             __nv_bfloat16* __restrict__ xht, __nv_bfloat16* __restrict__ xlt,
                             __nv_bfloat16* __restrict__ xhm, __nv_bfloat16* __restrict__ xlm)
{
    long idx = (long)blockIdx.x * 256 + threadIdx.x;
    if (blockIdx.y == 0) {
        long total = (long)BB * TTEXT * ADIM;
        if (idx >= total) return;
        float v = hs[idx];
        __nv_bfloat16 h = __float2bfloat16(v);
        xht[idx] = h;
        xlt[idx] = __float2bfloat16(v - __bfloat162float(h));
    } else {
        long total = (long)BB * TMEL * CIPM;
        if (idx >= total) return;
        long r = idx >> 7;               // / CIPM
        int  c = (int)(idx & 127);
        float v = (c < ODIM) ? ys[r * ODIM + c] : 0.f;
        __nv_bfloat16 h = __float2bfloat16(v);
        xhm[idx] = h;
        xlm[idx] = __float2bfloat16(v - __bfloat162float(h));
    }
}

// ---------------- merged weight split: all 5 tensors in one launch ----------------
__device__ __forceinline__ void wsplit_one(const float* W, __nv_bfloat16* Wh,
                                           __nv_bfloat16* Wl, int CIN, int CIP,
                                           int KS, int idx)
{
    int total = KS * 384 * CIP;
    if (idx >= total) return;
    int k   = idx / (384 * CIP);
    int rem = idx - k * 384 * CIP;
    int co  = rem / CIP;
    int ci  = rem - co * CIP;
    float v = (ci < CIN) ? W[((size_t)co * CIN + ci) * KS + k] : 0.f;
    __nv_bfloat16 h = __float2bfloat16(v);
    Wh[idx] = h;
    Wl[idx] = __float2bfloat16(v - __bfloat162float(h));
}

__global__ void wsplit_all_k(const float* tw1, const float* tw2, const float* mw1,
                             const float* mw2, const float* mw3,
                             __nv_bfloat16* wt1h, __nv_bfloat16* wt1l,
                             __nv_bfloat16* wt2h, __nv_bfloat16* wt2l,
                             __nv_bfloat16* wm1h, __nv_bfloat16* wm1l,
                             __nv_bfloat16* wm2h, __nv_bfloat16* wm2l,
                             __nv_bfloat16* wm3h, __nv_bfloat16* wm3l)
{
    int idx = blockIdx.x * 256 + threadIdx.x;
    switch (blockIdx.y) {
    case 0: wsplit_one(tw1, wt1h, wt1l, ADIM, ADIM, 3, idx); break;
    case 1: wsplit_one(tw2, wt2h, wt2l, ADIM, ADIM, 1, idx); break;
    case 2: wsplit_one(mw1, wm1h, wm1l, ODIM, CIPM, 3, idx); break;
    case 3: wsplit_one(mw2, wm2h, wm2l, ADIM, ADIM, 3, idx); break;
    case 4: wsplit_one(mw3, wm3h, wm3l, ADIM, ADIM, 1, idx); break;
    }
}

// ---------------- conv1d via mma.sync bf16 split (3-term compensation) ----------
#define CONV_SMEM (1024 + 2 * 65536)
template<int KS, int CIP, bool RELU>
__global__ __launch_bounds__(256)
void convmma_k(const __nv_bfloat16* __restrict__ Xh, const __nv_bfloat16* __restrict__ Xl,
               const __nv_bfloat16* __restrict__ Wh, const __nv_bfloat16* __restrict__ Wl,
               const float* __restrict__ bias,
               __nv_bfloat16* __restrict__ Oh, __nv_bfloat16* __restrict__ Ol, int T)
{
    constexpr int PAD = (KS - 1) / 2;
    constexpr int NC  = CIP / 64;
    constexpr int NS  = KS * NC;
    extern __shared__ char smem[];
    const unsigned int su = sm_u32(smem);

    const int tid  = threadIdx.x;
    const int lane = tid & 31;
    const int wid  = tid >> 5;
    const int wm   = wid & 1;
    const int wn   = wid >> 1;
    const int b    = blockIdx.z;
    const int t0   = blockIdx.x * 128;
    const int n0   = blockIdx.y * 128;

    float* sBias = (float*)smem;
    if (tid < 128) sBias[tid] = bias[n0 + tid];

    const int g  = lane >> 3, wi = lane & 7;
    const int arow = ((g & 1) << 3) + wi, acg = g >> 1;
    const int brow = ((g >> 1) << 3) + wi, bcg = g & 1;

    auto fill = [&](int step) {
        int s  = step & 1;
        int k  = step / NC;
        int ch = step - k * NC;
        unsigned int ah = su + 1024 + s * 65536;
        unsigned int al = ah + 16384, bh = ah + 32768, bl = ah + 49152;
        #pragma unroll
        for (int i = tid; i < 1024; i += 256) {
            int r = i >> 3, c = i & 7;
            unsigned int sw = sw128(r * 128 + c * 16);
            int t  = t0 + r + k - PAD;
            int tc = t < 0 ? 0 : (t >= T ? T - 1 : t);
            unsigned int ok = (t >= 0 && t < T) ? 16u : 0u;
            size_t src = ((size_t)b * T + tc) * CIP + ch * 64 + c * 8;
            cp16(ah + sw, Xh + src, ok);
            cp16(al + sw, Xl + src, ok);
            size_t wsrc = ((size_t)k * 384 + n0 + r) * CIP + ch * 64 + c * 8;
            cp16(bh + sw, Wh + wsrc, 16u);
            cp16(bl + sw, Wl + wsrc, 16u);
        }
        cp_commit();
    };

    float acc[4][4][4];
    #pragma unroll
    for (int i = 0; i < 4; i++)
        #pragma unroll
        for (int j = 0; j < 4; j++)
            #pragma unroll
            for (int e = 0; e < 4; e++) acc[i][j][e] = 0.f;

    fill(0);
    for (int step = 0; step < NS; step++) {
        int s = step & 1;
        if (step + 1 < NS) { fill(step + 1); cp_wait<1>(); }
        else               { cp_wait<0>(); }
        __syncthreads();

        unsigned int ab = su + 1024 + s * 65536;
        unsigned int albase = ab + 16384, bhbase = ab + 32768, blbase = ab + 49152;

        #pragma unroll
        for (int kq = 0; kq < 4; kq++) {
            unsigned int a_h[4][4], a_l[4][4], b_h[2][4], b_l[2][4];
            #pragma unroll
            for (int i = 0; i < 4; i++) {
                unsigned int bo = sw128((wm * 64 + i * 16 + arow) * 128
                                        + (kq * 2 + acg) * 16);
                ldsm4(a_h[i], ab + bo);
                ldsm4(a_l[i], albase + bo);
            }
            #pragma unroll
            for (int p = 0; p < 2; p++) {
                unsigned int bo = sw128((wn * 32 + p * 16 + brow) * 128
                                        + (kq * 2 + bcg) * 16);
                ldsm4(b_h[p], bhbase + bo);
                ldsm4(b_l[p], blbase + bo);
            }
            #pragma unroll
            for (int i = 0; i < 4; i++)
                #pragma unroll
                for (int j = 0; j < 4; j++) {
                    const unsigned int* bh2 = &b_h[j >> 1][(j & 1) * 2];
                    const unsigned int* bl2 = &b_l[j >> 1][(j & 1) * 2];
                    mma16816(acc[i][j], a_h[i], bh2);
                    mma16816(acc[i][j], a_h[i], bl2);
                    mma16816(acc[i][j], a_l[i], bh2);
                }
        }
        __syncthreads();
    }

    #pragma unroll
    for (int i = 0; i < 4; i++) {
        #pragma unroll
        for (int half = 0; half < 2; half++) {
            int t = t0 + wm * 64 + i * 16 + (lane >> 2) + half * 8;
            if (t >= T) continue;
            size_t base = ((size_t)b * T + t) * 384 + n0;
            #pragma unroll
            for (int j = 0; j < 4; j++) {
                int c = wn * 32 + j * 8 + (lane & 3) * 2;
                float v0 = acc[i][j][half * 2]     + sBias[c];
                float v1 = acc[i][j][half * 2 + 1] + sBias[c + 1];
                if (RELU) { v0 = fmaxf(v0, 0.f); v1 = fmaxf(v1, 0.f); }
                __nv_bfloat16 h0 = __float2bfloat16(v0);
                __nv_bfloat16 h1 = __float2bfloat16(v1);
                __nv_bfloat162 hp; hp.x = h0; hp.y = h1;
                __nv_bfloat162 lp;
                lp.x = __float2bfloat16(v0 - __bfloat162float(h0));
                lp.y = __float2bfloat16(v1 - __bfloat162float(h1));
                *(__nv_bfloat162*)&Oh[base + c] = hp;
                *(__nv_bfloat162*)&Ol[base + c] = lp;
            }
        }
    }
}

// ---------------- row squared-norms from hi/lo over 384 features ----------------
__global__ void rownorm2_k(const __nv_bfloat16* __restrict__ Xh,
                           const __nv_bfloat16* __restrict__ Xl,
                           float* __restrict__ Nrm)
{
    int row = blockIdx.x;
    const __nv_bfloat16* ph = Xh + (size_t)row * 384;
    const __nv_bfloat16* pl = Xl + (size_t)row * 384;
    float s = 0.f;
    for (int i = threadIdx.x; i < 384; i += 128) {
        float v = __bfloat162float(ph[i]) + __bfloat162float(pl[i]);
        s += v * v;
    }
    #pragma unroll
    for (int o = 16; o > 0; o >>= 1) s += __shfl_xor_sync(0xffffffffu, s, o);
    __shared__ float ps[4];
    if ((threadIdx.x & 31) == 0) ps[threadIdx.x >> 5] = s;
    __syncthreads();
    if (threadIdx.x == 0) Nrm[row] = ps[0] + ps[1] + ps[2] + ps[3];
}

// ---------------- fused distance mma-GEMM + sqrt + mask + log_softmax --------
// 2-term compensation here (Yh*Hh + Yh*Hl); Yl unused. Error ~5e-5 rel, OK.
#define ATTN_STAGE 69120
#define ATTN_SMEM  (2112 + 2 * ATTN_STAGE)
__global__ __launch_bounds__(256)
void attnmma_k(const __nv_bfloat16* __restrict__ Yh,
               const __nv_bfloat16* __restrict__ Hh, const __nv_bfloat16* __restrict__ Hl,
               const float* __restrict__ Yn, const float* __restrict__ Hn,
               const unsigned char* __restrict__ mask, float* __restrict__ Out)
{
    constexpr int NSTEP = ADIM / 32;   // 12
    extern __shared__ char smem[];
    float* sHnM = (float*)smem;                       // [400] (+inf where masked)
    float* sRed = (float*)(smem + 1600);              // [4][16][2]
    const unsigned int su = sm_u32(smem);

    const int tid  = threadIdx.x;
    const int lane = tid & 31;
    const int wid  = tid >> 5;
    const int wm   = wid & 3;       // 4 M groups of 16 rows
    const int wn   = wid >> 2;      // 2 N halves of 200 cols
    const int b    = blockIdx.y;
    const int m0   = blockIdx.x * 64;

    for (int i = tid; i < 400; i += 256)
        sHnM[i] = mask[b * TTEXT + i] ? __int_as_float(0x7f800000) : Hn[b * TTEXT + i];

    // stage layout (pitch 20 words/row): Yh[64][20] @0, Hh[400][20] @5120B, Hl @37120B
    auto fill = [&](int step) {
        int s = step & 1;
        int kc = step * 32;
        unsigned int st = su + 2112 + s * ATTN_STAGE;
        #pragma unroll 2
        for (int i = tid; i < 1600; i += 256) {        // H rows
            int n = i >> 2, q = i & 3;
            unsigned int dst = st + 5120 + (n * 20 + q * 4) * 4;
            size_t src = ((size_t)b * TTEXT + n) * ADIM + kc + q * 8;
            cp16(dst,         Hh + src, 16u);
            cp16(dst + 32000, Hl + src, 16u);
        }
        {
            int i = tid;                                // Y rows (256 tasks)
            int r = i >> 2, q = i & 3;
            unsigned int dst = st + (r * 20 + q * 4) * 4;
            size_t src = ((size_t)b * TMEL + m0 + r) * ADIM + kc + q * 8;
            cp16(dst, Yh + src, 16u);
        }
        cp_commit();
    };

    float acc[25][4];
    #pragma unroll
    for (int j = 0; j < 25; j++)
        #pragma unroll
        for (int e = 0; e < 4; e++) acc[j][e] = 0.f;

    const int r0 = lane >> 2;
    const int lw = lane & 3;

    fill(0);
    for (int step = 0; step < NSTEP; step++) {
        int s = step & 1;
        if (step + 1 < NSTEP) { fill(step + 1); cp_wait<1>(); }
        else                  { cp_wait<0>(); }
        __syncthreads();

        const unsigned int st = su + 2112 + s * ATTN_STAGE;
        const uint32_t* Ys_h = (const uint32_t*)(smem + (st - su));
        const uint32_t* Hs_h = Ys_h + 1280;            // 5120B
        const uint32_t* Hs_l = Hs_h + 8000;            // 32000B

        #pragma unroll
        for (int kq = 0; kq < 2; kq++) {
            const int w0 = kq * 8 + lw;
            unsigned int ah[4];
            {
                int ra = (wm * 16 + r0) * 20;
                int rb = (wm * 16 + r0 + 8) * 20;
                ah[0] = Ys_h[ra + w0];     ah[1] = Ys_h[rb + w0];
                ah[2] = Ys_h[ra + w0 + 4]; ah[3] = Ys_h[rb + w0 + 4];
            }
            #pragma unroll
            for (int j = 0; j < 25; j++) {
                int n = (wn * 200 + j * 8 + r0) * 20;
                unsigned int bh[2], bl[2];
                bh[0] = Hs_h[n + w0]; bh[1] = Hs_h[n + w0 + 4];
                bl[0] = Hs_l[n + w0]; bl[1] = Hs_l[n + w0 + 4];
                mma16816(acc[j], ah, bh);
                mma16816(acc[j], ah, bl);
            }
        }
        __syncthreads();
    }

    // ---- epilogue: scores + log_softmax ----
    int mrow0 = m0 + wm * 16 + r0;
    float yn0 = Yn[b * TMEL + mrow0];
    float yn1 = Yn[b * TMEL + mrow0 + 8];

    #pragma unroll
    for (int j = 0; j < 25; j++) {
        int c = wn * 200 + j * 8 + lw * 2;
        float hn0 = sHnM[c], hn1 = sHnM[c + 1];
        acc[j][0] = -sqrtf(fmaxf(yn0 + hn0 - 2.f * acc[j][0], 1e-12f));
        acc[j][1] = -sqrtf(fmaxf(yn0 + hn1 - 2.f * acc[j][1], 1e-12f));
        acc[j][2] = -sqrtf(fmaxf(yn1 + hn0 - 2.f * acc[j][2], 1e-12f));
        acc[j][3] = -sqrtf(fmaxf(yn1 + hn1 - 2.f * acc[j][3], 1e-12f));
    }

    float mx0 = -INFINITY, mx1 = -INFINITY;
    #pragma unroll
    for (int j = 0; j < 25; j++) {
        mx0 = fmaxf(mx0, fmaxf(acc[j][0], acc[j][1]));
        mx1 = fmaxf(mx1, fmaxf(acc[j][2], acc[j][3]));
    }
    #pragma unroll
    for (int o = 1; o <= 2; o <<= 1) {
        mx0 = fmaxf(mx0, __shfl_xor_sync(0xffffffffu, mx0, o));
        mx1 = fmaxf(mx1, __shfl_xor_sync(0xffffffffu, mx1, o));
    }
    if (lw == 0) {
        sRed[(wm * 16 + r0) * 2 + wn]     = mx0;
        sRed[(wm * 16 + r0 + 8) * 2 + wn] = mx1;
    }
    __syncthreads();
    mx0 = fmaxf(sRed[(wm * 16 + r0) * 2],     sRed[(wm * 16 + r0) * 2 + 1]);
    mx1 = fmaxf(sRed[(wm * 16 + r0 + 8) * 2], sRed[(wm * 16 + r0 + 8) * 2 + 1]);
    __syncthreads();

    float sm0 = 0.f, sm1 = 0.f;
    #pragma unroll
    for (int j = 0; j < 25; j++) {
        sm0 += __expf(acc[j][0] - mx0) + __expf(acc[j][1] - mx0);
        sm1 += __expf(acc[j][2] - mx1) + __expf(acc[j][3] - mx1);
    }
    #pragma unroll
    for (int o = 1; o <= 2; o <<= 1) {
        sm0 += __shfl_xor_sync(0xffffffffu, sm0, o);
        sm1 += __shfl_xor_sync(0xffffffffu, sm1, o);
    }
    if (lw == 0) {
        sRed[(wm * 16 + r0) * 2 + wn]     = sm0;
        sRed[(wm * 16 + r0 + 8) * 2 + wn] = sm1;
    }
    __syncthreads();
    sm0 = sRed[(wm * 16 + r0) * 2]     + sRed[(wm * 16 + r0) * 2 + 1];
    sm1 = sRed[(wm * 16 + r0 + 8) * 2] + sRed[(wm * 16 + r0 + 8) * 2 + 1];
    float lse0 = mx0 + __logf(sm0);
    float lse1 = mx1 + __logf(sm1);

    float* o0 = Out + ((size_t)b * TMEL + mrow0) * TTEXT;
    float* o1 = Out + ((size_t)b * TMEL + mrow0 + 8) * TTEXT;
    #pragma unroll
    for (int j = 0; j < 25; j++) {
        int c = wn * 200 + j * 8 + lw * 2;
        *(float2*)&o0[c] = make_float2(acc[j][0] - lse0, acc[j][1] - lse0);
        *(float2*)&o1[c] = make_float2(acc[j][2] - lse1, acc[j][3] - lse1);
    }
}

// ---------------- launch ----------------
extern "C" void kernel_launch(void* const* d_in, const int* in_sizes, int n_in,
                              void* d_out, int out_size)
{
    const float* hs   = (const float*)d_in[0];
    const float* ys   = (const float*)d_in[1];
    const unsigned char* mask = (const unsigned char*)d_in[2];
    const float* t_w1 = (const float*)d_in[3];
    const float* t_b1 = (const float*)d_in[4];
    const float* t_w2 = (const float*)d_in[5];
    const float* t_b2 = (const float*)d_in[6];
    const float* m_w1 = (const float*)d_in[7];
    const float* m_b1 = (const float*)d_in[8];
    const float* m_w2 = (const float*)d_in[9];
    const float* m_b2 = (const float*)d_in[10];
    const float* m_w3 = (const float*)d_in[11];
    const float* m_b3 = (const float*)d_in[12];
    float* out = (float*)d_out;

    __nv_bfloat16 *xht, *xlt, *h1h, *h1l, *xhm, *xlm, *y1h, *y1l, *y2h, *y2l;
    __nv_bfloat16 *wt1h, *wt1l, *wt2h, *wt2l, *wm1h, *wm1l, *wm2h, *wm2l, *wm3h, *wm3l;
    float *hn, *yn;
    cudaGetSymbolAddress((void**)&xht, g_xht); cudaGetSymbolAddress((void**)&xlt, g_xlt);
    cudaGetSymbolAddress((void**)&h1h, g_h1h); cudaGetSymbolAddress((void**)&h1l, g_h1l);
    cudaGetSymbolAddress((void**)&xhm, g_xhm); cudaGetSymbolAddress((void**)&xlm, g_xlm);
    cudaGetSymbolAddress((void**)&y1h, g_y1h); cudaGetSymbolAddress((void**)&y1l, g_y1l);
    cudaGetSymbolAddress((void**)&y2h, g_y2h); cudaGetSymbolAddress((void**)&y2l, g_y2l);
    cudaGetSymbolAddress((void**)&wt1h, g_wt1h); cudaGetSymbolAddress((void**)&wt1l, g_wt1l);
    cudaGetSymbolAddress((void**)&wt2h, g_wt2h); cudaGetSymbolAddress((void**)&wt2l, g_wt2l);
    cudaGetSymbolAddress((void**)&wm1h, g_wm1h); cudaGetSymbolAddress((void**)&wm1l, g_wm1l);
    cudaGetSymbolAddress((void**)&wm2h, g_wm2h); cudaGetSymbolAddress((void**)&wm2l, g_wm2l);
    cudaGetSymbolAddress((void**)&wm3h, g_wm3h); cudaGetSymbolAddress((void**)&wm3l, g_wm3l);
    cudaGetSymbolAddress((void**)&hn, g_hn);   cudaGetSymbolAddress((void**)&yn, g_yn);

    cudaFuncSetAttribute(convmma_k<3, 384, true >,
                         cudaFuncAttributeMaxDynamicSharedMemorySize, CONV_SMEM);
    cudaFuncSetAttribute(convmma_k<1, 384, false>,
                         cudaFuncAttributeMaxDynamicSharedMemorySize, CONV_SMEM);
    cudaFuncSetAttribute(convmma_k<3, 128, true >,
                         cudaFuncAttributeMaxDynamicSharedMemorySize, CONV_SMEM);
    cudaFuncSetAttribute(attnmma_k,
                         cudaFuncAttributeMaxDynamicSharedMemorySize, ATTN_SMEM);

    // #0: merged input split
    {
        long mel = (long)BB * TMEL * CIPM;   // 6.55M > text 4.9M
        dim3 g((unsigned)((mel + 255) / 256), 2);
        xsplit_all_k<<<g, 256>>>(hs, ys, xht, xlt, xhm, xlm);
    }
    // #1: merged weight split
    {
        dim3 g((3 * 384 * ADIM + 255) / 256, 5);
        wsplit_all_k<<<g, 256>>>(t_w1, t_w2, m_w1, m_w2, m_w3,
                                 wt1h, wt1l, wt2h, wt2l, wm1h, wm1l,
                                 wm2h, wm2l, wm3h, wm3l);
    }

    // #2-#3: text prenet
    {
        dim3 g((TTEXT + 127) / 128, 3, BB);
        convmma_k<3, 384, true ><<<g, 256, CONV_SMEM>>>(
            xht, xlt, wt1h, wt1l, t_b1, h1h, h1l, TTEXT);
        convmma_k<1, 384, false><<<g, 256, CONV_SMEM>>>(
            h1h, h1l, wt2h, wt2l, t_b2, xht, xlt, TTEXT);
    }
    // #4-#6: mel prenet (#5 = mel conv2, the ncu-profiled launch)
    {
        dim3 g((TMEL + 127) / 128, 3, BB);
        convmma_k<3, 128, true ><<<g, 256, CONV_SMEM>>>(
            xhm, xlm, wm1h, wm1l, m_b1, y1h, y1l, TMEL);
        convmma_k<3, 384, true ><<<g, 256, CONV_SMEM>>>(
            y1h, y1l, wm2h, wm2l, m_b2, y2h, y2l, TMEL);
        convmma_k<1, 384, false><<<g, 256, CONV_SMEM>>>(
            y2h, y2l, wm3h, wm3l, m_b3, y1h, y1l, TMEL);
    }

    // row norms from hi/lo
    rownorm2_k<<<BB * TTEXT, 128>>>(xht, xlt, hn);
    rownorm2_k<<<BB * TMEL, 128>>>(y1h, y1l, yn);

    // fused distance + log_softmax (tensor-core, 2-term)
    {
        dim3 g(TMEL / 64, BB);
        attnmma_k<<<g, 256, ATTN_SMEM>>>(y1h, xht, xlt, yn, hn, mask, out);
    }
}

// round 9
// speedup vs baseline: 4.6291x; 1.0597x over previous
#include <cuda_runtime.h>
#include <cuda_bf16.h>
#include <math.h>
#include <stdint.h>

#define BB    32
#define TTEXT 400
#define TMEL  1600
#define ADIM  384
#define ODIM  80
#define CIPM  128   // mel input channels padded 80 -> 128

// ---------------- static scratch (no allocations allowed) ----------------
__device__ __nv_bfloat16 g_xht[(size_t)BB * TTEXT * ADIM];
__device__ __nv_bfloat16 g_xlt[(size_t)BB * TTEXT * ADIM];
__device__ __nv_bfloat16 g_h1h[(size_t)BB * TTEXT * ADIM];
__device__ __nv_bfloat16 g_h1l[(size_t)BB * TTEXT * ADIM];
__device__ __nv_bfloat16 g_xhm[(size_t)BB * TMEL * CIPM];
__device__ __nv_bfloat16 g_xlm[(size_t)BB * TMEL * CIPM];
__device__ __nv_bfloat16 g_y1h[(size_t)BB * TMEL * ADIM];
__device__ __nv_bfloat16 g_y1l[(size_t)BB * TMEL * ADIM];
__device__ __nv_bfloat16 g_y2h[(size_t)BB * TMEL * ADIM];
__device__ __nv_bfloat16 g_y2l[(size_t)BB * TMEL * ADIM];
// weights bf16 hi/lo, layout [k][co][ci_padded]
__device__ __nv_bfloat16 g_wt1h[3 * 384 * ADIM], g_wt1l[3 * 384 * ADIM];
__device__ __nv_bfloat16 g_wt2h[1 * 384 * ADIM], g_wt2l[1 * 384 * ADIM];
__device__ __nv_bfloat16 g_wm1h[3 * 384 * CIPM], g_wm1l[3 * 384 * CIPM];
__device__ __nv_bfloat16 g_wm2h[3 * 384 * ADIM], g_wm2l[3 * 384 * ADIM];
__device__ __nv_bfloat16 g_wm3h[1 * 384 * ADIM], g_wm3l[1 * 384 * ADIM];
__device__ float g_hn[BB * TTEXT];
__device__ float g_yn[BB * TMEL];

// ---------------- PTX helpers (family-level only) ----------------
__device__ __forceinline__ unsigned int sm_u32(const void* p)
{
    return (unsigned int)__cvta_generic_to_shared(p);
}
__device__ __forceinline__ void cp16(unsigned int dst, const void* src,
                                     unsigned int bytes)
{
    asm volatile("cp.async.cg.shared.global [%0], [%1], 16, %2;"
                 :: "r"(dst), "l"(src), "r"(bytes) : "memory");
}
__device__ __forceinline__ void cp_commit()
{
    asm volatile("cp.async.commit_group;" ::: "memory");
}
template<int N>
__device__ __forceinline__ void cp_wait()
{
    asm volatile("cp.async.wait_group %0;" :: "n"(N) : "memory");
}
__device__ __forceinline__ void ldsm4(unsigned int* r, unsigned int addr)
{
    asm volatile("ldmatrix.sync.aligned.m8n8.x4.shared.b16 {%0,%1,%2,%3}, [%4];"
                 : "=r"(r[0]), "=r"(r[1]), "=r"(r[2]), "=r"(r[3]) : "r"(addr));
}
__device__ __forceinline__ void mma16816(float* c, const unsigned int* a,
                                         const unsigned int* b)
{
    asm volatile("mma.sync.aligned.m16n8k16.row.col.f32.bf16.bf16.f32 "
                 "{%0,%1,%2,%3}, {%4,%5,%6,%7}, {%8,%9}, {%0,%1,%2,%3};"
                 : "+f"(c[0]), "+f"(c[1]), "+f"(c[2]), "+f"(c[3])
                 : "r"(a[0]), "r"(a[1]), "r"(a[2]), "r"(a[3]),
                   "r"(b[0]), "r"(b[1]));
}
__device__ __forceinline__ unsigned int sw64(unsigned int bo)
{
    return bo ^ ((bo >> 3) & 0x30);
}

// ---------------- merged input split: text + mel in one launch ----------------
__global__ void xsplit_all_k(const float* __restrict__ hs, const float* __restrict__ ys,
                             __nv_bfloat16* __restrict__ xht, __nv_bfloat16* __restrict__ xlt,
                             __nv_bfloat16* __restrict__ xhm, __nv_bfloat16* __restrict__ xlm)
{
    long idx = (long)blockIdx.x * 256 + threadIdx.x;
    if (blockIdx.y == 0) {
        long total = (long)BB * TTEXT * ADIM;
        if (idx >= total) return;
        float v = hs[idx];
        __nv_bfloat16 h = __float2bfloat16(v);
        xht[idx] = h;
        xlt[idx] = __float2bfloat16(v - __bfloat162float(h));
    } else {
        long total = (long)BB * TMEL * CIPM;
        if (idx >= total) return;
        long r = idx >> 7;
        int  c = (int)(idx & 127);
        float v = (c < ODIM) ? ys[r * ODIM + c] : 0.f;
        __nv_bfloat16 h = __float2bfloat16(v);
        xhm[idx] = h;
        xlm[idx] = __float2bfloat16(v - __bfloat162float(h));
    }
}

// ---------------- merged weight split: all 5 tensors in one launch ----------------
__device__ __forceinline__ void wsplit_one(const float* W, __nv_bfloat16* Wh,
                                           __nv_bfloat16* Wl, int CIN, int CIP,
                                           int KS, int idx)
{
    int total = KS * 384 * CIP;
    if (idx >= total) return;
    int k   = idx / (384 * CIP);
    int rem = idx - k * 384 * CIP;
    int co  = rem / CIP;
    int ci  = rem - co * CIP;
    float v = (ci < CIN) ? W[((size_t)co * CIN + ci) * KS + k] : 0.f;
    __nv_bfloat16 h = __float2bfloat16(v);
    Wh[idx] = h;
    Wl[idx] = __float2bfloat16(v - __bfloat162float(h));
}

__global__ void wsplit_all_k(const float* tw1, const float* tw2, const float* mw1,
                             const float* mw2, const float* mw3,
                             __nv_bfloat16* wt1h, __nv_bfloat16* wt1l,
                             __nv_bfloat16* wt2h, __nv_bfloat16* wt2l,
                             __nv_bfloat16* wm1h, __nv_bfloat16* wm1l,
                             __nv_bfloat16* wm2h, __nv_bfloat16* wm2l,
                             __nv_bfloat16* wm3h, __nv_bfloat16* wm3l)
{
    int idx = blockIdx.x * 256 + threadIdx.x;
    switch (blockIdx.y) {
    case 0: wsplit_one(tw1, wt1h, wt1l, ADIM, ADIM, 3, idx); break;
    case 1: wsplit_one(tw2, wt2h, wt2l, ADIM, ADIM, 1, idx); break;
    case 2: wsplit_one(mw1, wm1h, wm1l, ODIM, CIPM, 3, idx); break;
    case 3: wsplit_one(mw2, wm2h, wm2l, ADIM, ADIM, 3, idx); break;
    case 4: wsplit_one(mw3, wm3h, wm3l, ADIM, ADIM, 1, idx); break;
    }
}

// ---------------- conv1d via mma.sync bf16 split (3-term compensation) ----------
// CTA tile: 64 time-rows x 128 couts, 8 warps (wm=wid&1: 32 rows, wn=wid>>1: 32 couts).
// K streamed in 32-channel chunks per tap; SW64 swizzle on 64B-pitch rows.
// Stage = Ah(4K)+Al(4K)+Bh(8K)+Bl(8K) = 24KB; 2 stages + bias -> 2 CTAs/SM.
#define CONV_SMEM (1024 + 2 * 24576)
template<int KS, int CIP, bool RELU>
__global__ __launch_bounds__(256, 2)
void convmma_k(const __nv_bfloat16* __restrict__ Xh, const __nv_bfloat16* __restrict__ Xl,
               const __nv_bfloat16* __restrict__ Wh, const __nv_bfloat16* __restrict__ Wl,
               const float* __restrict__ bias,
               __nv_bfloat16* __restrict__ Oh, __nv_bfloat16* __restrict__ Ol, int T)
{
    constexpr int PAD = (KS - 1) / 2;
    constexpr int NC  = CIP / 32;
    constexpr int NS  = KS * NC;
    extern __shared__ char smem[];
    const unsigned int su = sm_u32(smem);

    const int tid  = threadIdx.x;
    const int lane = tid & 31;
    const int wid  = tid >> 5;
    const int wm   = wid & 1;       // 2 groups of 32 time-rows
    const int wn   = wid >> 1;      // 4 groups of 32 couts
    const int b    = blockIdx.z;
    const int t0   = blockIdx.x * 64;
    const int n0   = blockIdx.y * 128;

    float* sBias = (float*)smem;
    if (tid < 128) sBias[tid] = bias[n0 + tid];

    const int g  = lane >> 3, wi = lane & 7;
    const int arow = ((g & 1) << 3) + wi, acg = g >> 1;
    const int brow = ((g >> 1) << 3) + wi, bcg = g & 1;

    // stage layout: Ah @0, Al @4096, Bh @8192, Bl @16384 (24KB total)
    auto fill = [&](int step) {
        int s  = step & 1;
        int k  = step / NC;
        int ch = step - k * NC;
        unsigned int st = su + 1024 + s * 24576;
        // A: 64 rows x 4 chunks x {hi,lo} = 512 tasks
        #pragma unroll
        for (int i = tid; i < 512; i += 256) {
            int tensor = i >> 8;
            int rem = i & 255;
            int r = rem >> 2, c = rem & 3;
            unsigned int sw = sw64(r * 64 + c * 16) + tensor * 4096;
            int t  = t0 + r + k - PAD;
            int tc = t < 0 ? 0 : (t >= T ? T - 1 : t);
            unsigned int ok = (t >= 0 && t < T) ? 16u : 0u;
            size_t src = ((size_t)b * T + tc) * CIP + ch * 32 + c * 8;
            cp16(st + sw, (tensor ? Xl : Xh) + src, ok);
        }
        // B: 128 rows x 4 chunks x {hi,lo} = 1024 tasks
        #pragma unroll
        for (int i = tid; i < 1024; i += 256) {
            int tensor = i >> 9;
            int rem = i & 511;
            int r = rem >> 2, c = rem & 3;
            unsigned int sw = 8192 + sw64(r * 64 + c * 16) + tensor * 8192;
            size_t src = ((size_t)k * 384 + n0 + r) * CIP + ch * 32 + c * 8;
            cp16(st + sw, (tensor ? Wl : Wh) + src, 16u);
        }
        cp_commit();
    };

    float acc[2][4][4];
    #pragma unroll
    for (int i = 0; i < 2; i++)
        #pragma unroll
        for (int j = 0; j < 4; j++)
            #pragma unroll
            for (int e = 0; e < 4; e++) acc[i][j][e] = 0.f;

    fill(0);
    for (int step = 0; step < NS; step++) {
        int s = step & 1;
        if (step + 1 < NS) { fill(step + 1); cp_wait<1>(); }
        else               { cp_wait<0>(); }
        __syncthreads();

        unsigned int st = su + 1024 + s * 24576;

        #pragma unroll
        for (int kq = 0; kq < 2; kq++) {
            unsigned int a_h[2][4], a_l[2][4], b_h[2][4], b_l[2][4];
            #pragma unroll
            for (int i = 0; i < 2; i++) {
                unsigned int bo = sw64((wm * 32 + i * 16 + arow) * 64
                                       + (kq * 2 + acg) * 16);
                ldsm4(a_h[i], st + bo);
                ldsm4(a_l[i], st + 4096 + bo);
            }
            #pragma unroll
            for (int p = 0; p < 2; p++) {
                unsigned int bo = sw64((wn * 32 + p * 16 + brow) * 64
                                       + (kq * 2 + bcg) * 16);
                ldsm4(b_h[p], st + 8192 + bo);
                ldsm4(b_l[p], st + 16384 + bo);
            }
            #pragma unroll
            for (int i = 0; i < 2; i++)
                #pragma unroll
                for (int j = 0; j < 4; j++) {
                    const unsigned int* bh2 = &b_h[j >> 1][(j & 1) * 2];
                    const unsigned int* bl2 = &b_l[j >> 1][(j & 1) * 2];
                    mma16816(acc[i][j], a_h[i], bh2);
                    mma16816(acc[i][j], a_h[i], bl2);
                    mma16816(acc[i][j], a_l[i], bh2);
                }
        }
        __syncthreads();
    }

    #pragma unroll
    for (int i = 0; i < 2; i++) {
        #pragma unroll
        for (int half = 0; half < 2; half++) {
            int t = t0 + wm * 32 + i * 16 + (lane >> 2) + half * 8;
            if (t >= T) continue;
            size_t base = ((size_t)b * T + t) * 384 + n0;
            #pragma unroll
            for (int j = 0; j < 4; j++) {
                int c = wn * 32 + j * 8 + (lane & 3) * 2;
                float v0 = acc[i][j][half * 2]     + sBias[c];
                float v1 = acc[i][j][half * 2 + 1] + sBias[c + 1];
                if (RELU) { v0 = fmaxf(v0, 0.f); v1 = fmaxf(v1, 0.f); }
                __nv_bfloat16 h0 = __float2bfloat16(v0);
                __nv_bfloat16 h1 = __float2bfloat16(v1);
                __nv_bfloat162 hp; hp.x = h0; hp.y = h1;
                __nv_bfloat162 lp;
                lp.x = __float2bfloat16(v0 - __bfloat162float(h0));
                lp.y = __float2bfloat16(v1 - __bfloat162float(h1));
                *(__nv_bfloat162*)&Oh[base + c] = hp;
                *(__nv_bfloat162*)&Ol[base + c] = lp;
            }
        }
    }
}

// ---------------- row squared-norms from hi/lo over 384 features ----------------
__global__ void rownorm2_k(const __nv_bfloat16* __restrict__ Xh,
                           const __nv_bfloat16* __restrict__ Xl,
                           float* __restrict__ Nrm)
{
    int row = blockIdx.x;
    const __nv_bfloat16* ph = Xh + (size_t)row * 384;
    const __nv_bfloat16* pl = Xl + (size_t)row * 384;
    float s = 0.f;
    for (int i = threadIdx.x; i < 384; i += 128) {
        float v = __bfloat162float(ph[i]) + __bfloat162float(pl[i]);
        s += v * v;
    }
    #pragma unroll
    for (int o = 16; o > 0; o >>= 1) s += __shfl_xor_sync(0xffffffffu, s, o);
    __shared__ float ps[4];
    if ((threadIdx.x & 31) == 0) ps[threadIdx.x >> 5] = s;
    __syncthreads();
    if (threadIdx.x == 0) Nrm[row] = ps[0] + ps[1] + ps[2] + ps[3];
}

// ---------------- fused distance mma-GEMM + sqrt + mask + log_softmax --------
// 2-term compensation here (Yh*Hh + Yh*Hl); Yl unused.
#define ATTN_STAGE 69120
#define ATTN_SMEM  (2112 + 2 * ATTN_STAGE)
__global__ __launch_bounds__(256)
void attnmma_k(const __nv_bfloat16* __restrict__ Yh,
               const __nv_bfloat16* __restrict__ Hh, const __nv_bfloat16* __restrict__ Hl,
               const float* __restrict__ Yn, const float* __restrict__ Hn,
               const unsigned char* __restrict__ mask, float* __restrict__ Out)
{
    constexpr int NSTEP = ADIM / 32;   // 12
    extern __shared__ char smem[];
    float* sHnM = (float*)smem;
    float* sRed = (float*)(smem + 1600);
    const unsigned int su = sm_u32(smem);

    const int tid  = threadIdx.x;
    const int lane = tid & 31;
    const int wid  = tid >> 5;
    const int wm   = wid & 3;
    const int wn   = wid >> 2;
    const int b    = blockIdx.y;
    const int m0   = blockIdx.x * 64;

    for (int i = tid; i < 400; i += 256)
        sHnM[i] = mask[b * TTEXT + i] ? __int_as_float(0x7f800000) : Hn[b * TTEXT + i];

    auto fill = [&](int step) {
        int s = step & 1;
        int kc = step * 32;
        unsigned int st = su + 2112 + s * ATTN_STAGE;
        #pragma unroll 2
        for (int i = tid; i < 1600; i += 256) {
            int n = i >> 2, q = i & 3;
            unsigned int dst = st + 5120 + (n * 20 + q * 4) * 4;
            size_t src = ((size_t)b * TTEXT + n) * ADIM + kc + q * 8;
            cp16(dst,         Hh + src, 16u);
            cp16(dst + 32000, Hl + src, 16u);
        }
        {
            int i = tid;
            int r = i >> 2, q = i & 3;
            unsigned int dst = st + (r * 20 + q * 4) * 4;
            size_t src = ((size_t)b * TMEL + m0 + r) * ADIM + kc + q * 8;
            cp16(dst, Yh + src, 16u);
        }
        cp_commit();
    };

    float acc[25][4];
    #pragma unroll
    for (int j = 0; j < 25; j++)
        #pragma unroll
        for (int e = 0; e < 4; e++) acc[j][e] = 0.f;

    const int r0 = lane >> 2;
    const int lw = lane & 3;

    fill(0);
    for (int step = 0; step < NSTEP; step++) {
        int s = step & 1;
        if (step + 1 < NSTEP) { fill(step + 1); cp_wait<1>(); }
        else                  { cp_wait<0>(); }
        __syncthreads();

        const unsigned int st = su + 2112 + s * ATTN_STAGE;
        const uint32_t* Ys_h = (const uint32_t*)(smem + (st - su));
        const uint32_t* Hs_h = Ys_h + 1280;
        const uint32_t* Hs_l = Hs_h + 8000;

        #pragma unroll
        for (int kq = 0; kq < 2; kq++) {
            const int w0 = kq * 8 + lw;
            unsigned int ah[4];
            {
                int ra = (wm * 16 + r0) * 20;
                int rb = (wm * 16 + r0 + 8) * 20;
                ah[0] = Ys_h[ra + w0];     ah[1] = Ys_h[rb + w0];
                ah[2] = Ys_h[ra + w0 + 4]; ah[3] = Ys_h[rb + w0 + 4];
            }
            #pragma unroll
            for (int j = 0; j < 25; j++) {
                int n = (wn * 200 + j * 8 + r0) * 20;
                unsigned int bh[2], bl[2];
                bh[0] = Hs_h[n + w0]; bh[1] = Hs_h[n + w0 + 4];
                bl[0] = Hs_l[n + w0]; bl[1] = Hs_l[n + w0 + 4];
                mma16816(acc[j], ah, bh);
                mma16816(acc[j], ah, bl);
            }
        }
        __syncthreads();
    }

    int mrow0 = m0 + wm * 16 + r0;
    float yn0 = Yn[b * TMEL + mrow0];
    float yn1 = Yn[b * TMEL + mrow0 + 8];

    #pragma unroll
    for (int j = 0; j < 25; j++) {
        int c = wn * 200 + j * 8 + lw * 2;
        float hn0 = sHnM[c], hn1 = sHnM[c + 1];
        acc[j][0] = -sqrtf(fmaxf(yn0 + hn0 - 2.f * acc[j][0], 1e-12f));
        acc[j][1] = -sqrtf(fmaxf(yn0 + hn1 - 2.f * acc[j][1], 1e-12f));
        acc[j][2] = -sqrtf(fmaxf(yn1 + hn0 - 2.f * acc[j][2], 1e-12f));
        acc[j][3] = -sqrtf(fmaxf(yn1 + hn1 - 2.f * acc[j][3], 1e-12f));
    }

    float mx0 = -INFINITY, mx1 = -INFINITY;
    #pragma unroll
    for (int j = 0; j < 25; j++) {
        mx0 = fmaxf(mx0, fmaxf(acc[j][0], acc[j][1]));
        mx1 = fmaxf(mx1, fmaxf(acc[j][2], acc[j][3]));
    }
    #pragma unroll
    for (int o = 1; o <= 2; o <<= 1) {
        mx0 = fmaxf(mx0, __shfl_xor_sync(0xffffffffu, mx0, o));
        mx1 = fmaxf(mx1, __shfl_xor_sync(0xffffffffu, mx1, o));
    }
    if (lw == 0) {
        sRed[(wm * 16 + r0) * 2 + wn]     = mx0;
        sRed[(wm * 16 + r0 + 8) * 2 + wn] = mx1;
    }
    __syncthreads();
    mx0 = fmaxf(sRed[(wm * 16 + r0) * 2],     sRed[(wm * 16 + r0) * 2 + 1]);
    mx1 = fmaxf(sRed[(wm * 16 + r0 + 8) * 2], sRed[(wm * 16 + r0 + 8) * 2 + 1]);
    __syncthreads();

    float sm0 = 0.f, sm1 = 0.f;
    #pragma unroll
    for (int j = 0; j < 25; j++) {
        sm0 += __expf(acc[j][0] - mx0) + __expf(acc[j][1] - mx0);
        sm1 += __expf(acc[j][2] - mx1) + __expf(acc[j][3] - mx1);
    }
    #pragma unroll
    for (int o = 1; o <= 2; o <<= 1) {
        sm0 += __shfl_xor_sync(0xffffffffu, sm0, o);
        sm1 += __shfl_xor_sync(0xffffffffu, sm1, o);
    }
    if (lw == 0) {
        sRed[(wm * 16 + r0) * 2 + wn]     = sm0;
        sRed[(wm * 16 + r0 + 8) * 2 + wn] = sm1;
    }
    __syncthreads();
    sm0 = sRed[(wm * 16 + r0) * 2]     + sRed[(wm * 16 + r0) * 2 + 1];
    sm1 = sRed[(wm * 16 + r0 + 8) * 2] + sRed[(wm * 16 + r0 + 8) * 2 + 1];
    float lse0 = mx0 + __logf(sm0);
    float lse1 = mx1 + __logf(sm1);

    float* o0 = Out + ((size_t)b * TMEL + mrow0) * TTEXT;
    float* o1 = Out + ((size_t)b * TMEL + mrow0 + 8) * TTEXT;
    #pragma unroll
    for (int j = 0; j < 25; j++) {
        int c = wn * 200 + j * 8 + lw * 2;
        *(float2*)&o0[c] = make_float2(acc[j][0] - lse0, acc[j][1] - lse0);
        *(float2*)&o1[c] = make_float2(acc[j][2] - lse1, acc[j][3] - lse1);
    }
}

// ---------------- launch ----------------
extern "C" void kernel_launch(void* const* d_in, const int* in_sizes, int n_in,
                              void* d_out, int out_size)
{
    const float* hs   = (const float*)d_in[0];
    const float* ys   = (const float*)d_in[1];
    const unsigned char* mask = (const unsigned char*)d_in[2];
    const float* t_w1 = (const float*)d_in[3];
    const float* t_b1 = (const float*)d_in[4];
    const float* t_w2 = (const float*)d_in[5];
    const float* t_b2 = (const float*)d_in[6];
    const float* m_w1 = (const float*)d_in[7];
    const float* m_b1 = (const float*)d_in[8];
    const float* m_w2 = (const float*)d_in[9];
    const float* m_b2 = (const float*)d_in[10];
    const float* m_w3 = (const float*)d_in[11];
    const float* m_b3 = (const float*)d_in[12];
    float* out = (float*)d_out;

    __nv_bfloat16 *xht, *xlt, *h1h, *h1l, *xhm, *xlm, *y1h, *y1l, *y2h, *y2l;
    __nv_bfloat16 *wt1h, *wt1l, *wt2h, *wt2l, *wm1h, *wm1l, *wm2h, *wm2l, *wm3h, *wm3l;
    float *hn, *yn;
    cudaGetSymbolAddress((void**)&xht, g_xht); cudaGetSymbolAddress((void**)&xlt, g_xlt);
    cudaGetSymbolAddress((void**)&h1h, g_h1h); cudaGetSymbolAddress((void**)&h1l, g_h1l);
    cudaGetSymbolAddress((void**)&xhm, g_xhm); cudaGetSymbolAddress((void**)&xlm, g_xlm);
    cudaGetSymbolAddress((void**)&y1h, g_y1h); cudaGetSymbolAddress((void**)&y1l, g_y1l);
    cudaGetSymbolAddress((void**)&y2h, g_y2h); cudaGetSymbolAddress((void**)&y2l, g_y2l);
    cudaGetSymbolAddress((void**)&wt1h, g_wt1h); cudaGetSymbolAddress((void**)&wt1l, g_wt1l);
    cudaGetSymbolAddress((void**)&wt2h, g_wt2h); cudaGetSymbolAddress((void**)&wt2l, g_wt2l);
    cudaGetSymbolAddress((void**)&wm1h, g_wm1h); cudaGetSymbolAddress((void**)&wm1l, g_wm1l);
    cudaGetSymbolAddress((void**)&wm2h, g_wm2h); cudaGetSymbolAddress((void**)&wm2l, g_wm2l);
    cudaGetSymbolAddress((void**)&wm3h, g_wm3h); cudaGetSymbolAddress((void**)&wm3l, g_wm3l);
    cudaGetSymbolAddress((void**)&hn, g_hn);   cudaGetSymbolAddress((void**)&yn, g_yn);

    cudaFuncSetAttribute(convmma_k<3, 384, true >,
                         cudaFuncAttributeMaxDynamicSharedMemorySize, CONV_SMEM);
    cudaFuncSetAttribute(convmma_k<1, 384, false>,
                         cudaFuncAttributeMaxDynamicSharedMemorySize, CONV_SMEM);
    cudaFuncSetAttribute(convmma_k<3, 128, true >,
                         cudaFuncAttributeMaxDynamicSharedMemorySize, CONV_SMEM);
    cudaFuncSetAttribute(attnmma_k,
                         cudaFuncAttributeMaxDynamicSharedMemorySize, ATTN_SMEM);

    // #0: merged input split
    {
        long mel = (long)BB * TMEL * CIPM;
        dim3 g((unsigned)((mel + 255) / 256), 2);
        xsplit_all_k<<<g, 256>>>(hs, ys, xht, xlt, xhm, xlm);
    }
    // #1: merged weight split
    {
        dim3 g((3 * 384 * ADIM + 255) / 256, 5);
        wsplit_all_k<<<g, 256>>>(t_w1, t_w2, m_w1, m_w2, m_w3,
                                 wt1h, wt1l, wt2h, wt2l, wm1h, wm1l,
                                 wm2h, wm2l, wm3h, wm3l);
    }

    // #2-#3: text prenet
    {
        dim3 g((TTEXT + 63) / 64, 3, BB);
        convmma_k<3, 384, true ><<<g, 256, CONV_SMEM>>>(
            xht, xlt, wt1h, wt1l, t_b1, h1h, h1l, TTEXT);
        convmma_k<1, 384, false><<<g, 256, CONV_SMEM>>>(
            h1h, h1l, wt2h, wt2l, t_b2, xht, xlt, TTEXT);
    }
    // #4-#6: mel prenet (#5 = mel conv2, the ncu-profiled launch)
    {
        dim3 g((TMEL + 63) / 64, 3, BB);
        convmma_k<3, 128, true ><<<g, 256, CONV_SMEM>>>(
            xhm, xlm, wm1h, wm1l, m_b1, y1h, y1l, TMEL);
        convmma_k<3, 384, true ><<<g, 256, CONV_SMEM>>>(
            y1h, y1l, wm2h, wm2l, m_b2, y2h, y2l, TMEL);
        convmma_k<1, 384, false><<<g, 256, CONV_SMEM>>>(
            y2h, y2l, wm3h, wm3l, m_b3, y1h, y1l, TMEL);
    }

    // row norms from hi/lo
    rownorm2_k<<<BB * TTEXT, 128>>>(xht, xlt, hn);
    rownorm2_k<<<BB * TMEL, 128>>>(y1h, y1l, yn);

    // fused distance + log_softmax (tensor-core, 2-term)
    {
        dim3 g(TMEL / 64, BB);
        attnmma_k<<<g, 256, ATTN_SMEM>>>(y1h, xht, xlt, yn, hn, mask, out);
    }
}

// round 10
// speedup vs baseline: 6.1988x; 1.3391x over previous
#include <cuda_runtime.h>
#include <cuda_bf16.h>
#include <math.h>
#include <stdint.h>

#define BB    32
#define TTEXT 400
#define TMEL  1600
#define ADIM  384
#define ODIM  80
#define CIPM  128   // mel input channels padded 80 -> 128

// ---------------- static scratch (no allocations allowed) ----------------
__device__ __nv_bfloat16 g_xht[(size_t)BB * TTEXT * ADIM];   // text conv2 out hi (attn H hi)
__device__ __nv_bfloat16 g_xlt[(size_t)BB * TTEXT * ADIM];   // text conv2 out lo (attn H lo)
__device__ __nv_bfloat16 g_xin[(size_t)BB * TTEXT * ADIM];   // text input hi
__device__ __nv_bfloat16 g_h1h[(size_t)BB * TTEXT * ADIM];
__device__ __nv_bfloat16 g_xhm[(size_t)BB * TMEL * CIPM];    // mel input hi (padded)
__device__ __nv_bfloat16 g_y1h[(size_t)BB * TMEL * ADIM];
__device__ __nv_bfloat16 g_y2h[(size_t)BB * TMEL * ADIM];
// weights bf16 hi/lo, layout [k][co][ci_padded]
__device__ __nv_bfloat16 g_wt1h[3 * 384 * ADIM], g_wt1l[3 * 384 * ADIM];
__device__ __nv_bfloat16 g_wt2h[1 * 384 * ADIM], g_wt2l[1 * 384 * ADIM];
__device__ __nv_bfloat16 g_wm1h[3 * 384 * CIPM], g_wm1l[3 * 384 * CIPM];
__device__ __nv_bfloat16 g_wm2h[3 * 384 * ADIM], g_wm2l[3 * 384 * ADIM];
__device__ __nv_bfloat16 g_wm3h[1 * 384 * ADIM], g_wm3l[1 * 384 * ADIM];
__device__ float g_hn[BB * TTEXT];
__device__ float g_yn[BB * TMEL];

// ---------------- PTX helpers (family-level only) ----------------
__device__ __forceinline__ unsigned int sm_u32(const void* p)
{
    return (unsigned int)__cvta_generic_to_shared(p);
}
__device__ __forceinline__ void cp16(unsigned int dst, const void* src,
                                     unsigned int bytes)
{
    asm volatile("cp.async.cg.shared.global [%0], [%1], 16, %2;"
                 :: "r"(dst), "l"(src), "r"(bytes) : "memory");
}
__device__ __forceinline__ void cp_commit()
{
    asm volatile("cp.async.commit_group;" ::: "memory");
}
template<int N>
__device__ __forceinline__ void cp_wait()
{
    asm volatile("cp.async.wait_group %0;" :: "n"(N) : "memory");
}
__device__ __forceinline__ void ldsm4(unsigned int* r, unsigned int addr)
{
    asm volatile("ldmatrix.sync.aligned.m8n8.x4.shared.b16 {%0,%1,%2,%3}, [%4];"
                 : "=r"(r[0]), "=r"(r[1]), "=r"(r[2]), "=r"(r[3]) : "r"(addr));
}
__device__ __forceinline__ void mma16816(float* c, const unsigned int* a,
                                         const unsigned int* b)
{
    asm volatile("mma.sync.aligned.m16n8k16.row.col.f32.bf16.bf16.f32 "
                 "{%0,%1,%2,%3}, {%4,%5,%6,%7}, {%8,%9}, {%0,%1,%2,%3};"
                 : "+f"(c[0]), "+f"(c[1]), "+f"(c[2]), "+f"(c[3])
                 : "r"(a[0]), "r"(a[1]), "r"(a[2]), "r"(a[3]),
                   "r"(b[0]), "r"(b[1]));
}
__device__ __forceinline__ unsigned int sw64(unsigned int bo)
{
    return bo ^ ((bo >> 3) & 0x30);
}

// ---------------- merged input split: hi only (A-side operands) ----------------
__global__ void xsplit_all_k(const float* __restrict__ hs, const float* __restrict__ ys,
                             __nv_bfloat16* __restrict__ xin, __nv_bfloat16* __restrict__ xhm)
{
    long idx = (long)blockIdx.x * 256 + threadIdx.x;
    if (blockIdx.y == 0) {
        long total = (long)BB * TTEXT * ADIM;
        if (idx >= total) return;
        xin[idx] = __float2bfloat16(hs[idx]);
    } else {
        long total = (long)BB * TMEL * CIPM;
        if (idx >= total) return;
        long r = idx >> 7;
        int  c = (int)(idx & 127);
        xhm[idx] = __float2bfloat16((c < ODIM) ? ys[r * ODIM + c] : 0.f);
    }
}

// ---------------- merged weight split: all 5 tensors (hi+lo, B-side) -------------
__device__ __forceinline__ void wsplit_one(const float* W, __nv_bfloat16* Wh,
                                           __nv_bfloat16* Wl, int CIN, int CIP,
                                           int KS, int idx)
{
    int total = KS * 384 * CIP;
    if (idx >= total) return;
    int k   = idx / (384 * CIP);
    int rem = idx - k * 384 * CIP;
    int co  = rem / CIP;
    int ci  = rem - co * CIP;
    float v = (ci < CIN) ? W[((size_t)co * CIN + ci) * KS + k] : 0.f;
    __nv_bfloat16 h = __float2bfloat16(v);
    Wh[idx] = h;
    Wl[idx] = __float2bfloat16(v - __bfloat162float(h));
}

__global__ void wsplit_all_k(const float* tw1, const float* tw2, const float* mw1,
                             const float* mw2, const float* mw3,
                             __nv_bfloat16* wt1h, __nv_bfloat16* wt1l,
                             __nv_bfloat16* wt2h, __nv_bfloat16* wt2l,
                             __nv_bfloat16* wm1h, __nv_bfloat16* wm1l,
                             __nv_bfloat16* wm2h, __nv_bfloat16* wm2l,
                             __nv_bfloat16* wm3h, __nv_bfloat16* wm3l)
{
    int idx = blockIdx.x * 256 + threadIdx.x;
    switch (blockIdx.y) {
    case 0: wsplit_one(tw1, wt1h, wt1l, ADIM, ADIM, 3, idx); break;
    case 1: wsplit_one(tw2, wt2h, wt2l, ADIM, ADIM, 1, idx); break;
    case 2: wsplit_one(mw1, wm1h, wm1l, ODIM, CIPM, 3, idx); break;
    case 3: wsplit_one(mw2, wm2h, wm2l, ADIM, ADIM, 3, idx); break;
    case 4: wsplit_one(mw3, wm3h, wm3l, ADIM, ADIM, 1, idx); break;
    }
}

// ---------------- conv1d via mma.sync, 2-term compensation (Ah*Bh + Ah*Bl) ------
// CTA tile: 64 time-rows x 128 couts, 8 warps. 3-stage cp.async pipeline,
// single __syncthreads per K-step. Stage = Ah(4K)+Bh(8K)+Bl(8K) = 20KB.
#define CONV_SMEM (1024 + 3 * 20480)
template<int KS, int CIP, bool RELU, bool SPLITLO>
__global__ __launch_bounds__(256, 2)
void convmma_k(const __nv_bfloat16* __restrict__ Xh,
               const __nv_bfloat16* __restrict__ Wh, const __nv_bfloat16* __restrict__ Wl,
               const float* __restrict__ bias,
               __nv_bfloat16* __restrict__ Oh, __nv_bfloat16* __restrict__ Ol, int T)
{
    constexpr int PAD = (KS - 1) / 2;
    constexpr int NC  = CIP / 32;
    constexpr int NS  = KS * NC;
    extern __shared__ char smem[];
    const unsigned int su = sm_u32(smem);

    const int tid  = threadIdx.x;
    const int lane = tid & 31;
    const int wid  = tid >> 5;
    const int wm   = wid & 1;       // 2 groups of 32 time-rows
    const int wn   = wid >> 1;      // 4 groups of 32 couts
    const int b    = blockIdx.z;
    const int t0   = blockIdx.x * 64;
    const int n0   = blockIdx.y * 128;

    float* sBias = (float*)smem;
    if (tid < 128) sBias[tid] = bias[n0 + tid];

    const int g  = lane >> 3, wi = lane & 7;
    const int arow = ((g & 1) << 3) + wi, acg = g >> 1;
    const int brow = ((g >> 1) << 3) + wi, bcg = g & 1;

    // stage layout: Ah @0 (4KB), Bh @4096 (8KB), Bl @12288 (8KB)
    auto fill = [&](int step) {
        int s  = step % 3;
        int k  = step / NC;
        int ch = step - k * NC;
        unsigned int st = su + 1024 + s * 20480;
        // A: 64 rows x 4 chunks = 256 tasks
        {
            int r = tid >> 2, c = tid & 3;
            unsigned int sw = sw64(r * 64 + c * 16);
            int t  = t0 + r + k - PAD;
            int tc = t < 0 ? 0 : (t >= T ? T - 1 : t);
            unsigned int ok = (t >= 0 && t < T) ? 16u : 0u;
            size_t src = ((size_t)b * T + tc) * CIP + ch * 32 + c * 8;
            cp16(st + sw, Xh + src, ok);
        }
        // B: 128 rows x 4 chunks x {hi,lo} = 1024 tasks
        #pragma unroll
        for (int i = tid; i < 1024; i += 256) {
            int tensor = i >> 9;
            int rem = i & 511;
            int r = rem >> 2, c = rem & 3;
            unsigned int sw = 4096 + sw64(r * 64 + c * 16) + tensor * 8192;
            size_t src = ((size_t)k * 384 + n0 + r) * CIP + ch * 32 + c * 8;
            cp16(st + sw, (tensor ? Wl : Wh) + src, 16u);
        }
        cp_commit();
    };

    float acc[2][4][4];
    #pragma unroll
    for (int i = 0; i < 2; i++)
        #pragma unroll
        for (int j = 0; j < 4; j++)
            #pragma unroll
            for (int e = 0; e < 4; e++) acc[i][j][e] = 0.f;

    fill(0);
    if (NS > 1) fill(1);
    for (int step = 0; step < NS; step++) {
        if (step == NS - 1) cp_wait<0>();
        else                cp_wait<1>();
        __syncthreads();
        if (step + 2 < NS) fill(step + 2);

        unsigned int st = su + 1024 + (step % 3) * 20480;

        #pragma unroll
        for (int kq = 0; kq < 2; kq++) {
            unsigned int a_h[2][4], b_h[2][4], b_l[2][4];
            #pragma unroll
            for (int i = 0; i < 2; i++) {
                unsigned int bo = sw64((wm * 32 + i * 16 + arow) * 64
                                       + (kq * 2 + acg) * 16);
                ldsm4(a_h[i], st + bo);
            }
            #pragma unroll
            for (int p = 0; p < 2; p++) {
                unsigned int bo = sw64((wn * 32 + p * 16 + brow) * 64
                                       + (kq * 2 + bcg) * 16);
                ldsm4(b_h[p], st + 4096 + bo);
                ldsm4(b_l[p], st + 12288 + bo);
            }
            #pragma unroll
            for (int i = 0; i < 2; i++)
                #pragma unroll
                for (int j = 0; j < 4; j++) {
                    const unsigned int* bh2 = &b_h[j >> 1][(j & 1) * 2];
                    const unsigned int* bl2 = &b_l[j >> 1][(j & 1) * 2];
                    mma16816(acc[i][j], a_h[i], bh2);
                    mma16816(acc[i][j], a_h[i], bl2);
                }
        }
    }

    #pragma unroll
    for (int i = 0; i < 2; i++) {
        #pragma unroll
        for (int half = 0; half < 2; half++) {
            int t = t0 + wm * 32 + i * 16 + (lane >> 2) + half * 8;
            if (t >= T) continue;
            size_t base = ((size_t)b * T + t) * 384 + n0;
            #pragma unroll
            for (int j = 0; j < 4; j++) {
                int c = wn * 32 + j * 8 + (lane & 3) * 2;
                float v0 = acc[i][j][half * 2]     + sBias[c];
                float v1 = acc[i][j][half * 2 + 1] + sBias[c + 1];
                if (RELU) { v0 = fmaxf(v0, 0.f); v1 = fmaxf(v1, 0.f); }
                __nv_bfloat16 h0 = __float2bfloat16(v0);
                __nv_bfloat16 h1 = __float2bfloat16(v1);
                __nv_bfloat162 hp; hp.x = h0; hp.y = h1;
                *(__nv_bfloat162*)&Oh[base + c] = hp;
                if (SPLITLO) {
                    __nv_bfloat162 lp;
                    lp.x = __float2bfloat16(v0 - __bfloat162float(h0));
                    lp.y = __float2bfloat16(v1 - __bfloat162float(h1));
                    *(__nv_bfloat162*)&Ol[base + c] = lp;
                }
            }
        }
    }
}

// ---------------- row squared-norms (lo optional) over 384 features -------------
__global__ void rownorm2_k(const __nv_bfloat16* __restrict__ Xh,
                           const __nv_bfloat16* __restrict__ Xl,
                           float* __restrict__ Nrm)
{
    int row = blockIdx.x;
    const __nv_bfloat16* ph = Xh + (size_t)row * 384;
    const __nv_bfloat16* pl = Xl ? Xl + (size_t)row * 384 : nullptr;
    float s = 0.f;
    for (int i = threadIdx.x; i < 384; i += 128) {
        float v = __bfloat162float(ph[i]);
        if (pl) v += __bfloat162float(pl[i]);
        s += v * v;
    }
    #pragma unroll
    for (int o = 16; o > 0; o >>= 1) s += __shfl_xor_sync(0xffffffffu, s, o);
    __shared__ float ps[4];
    if ((threadIdx.x & 31) == 0) ps[threadIdx.x >> 5] = s;
    __syncthreads();
    if (threadIdx.x == 0) Nrm[row] = ps[0] + ps[1] + ps[2] + ps[3];
}

// ---------------- fused distance mma-GEMM + sqrt + mask + log_softmax --------
// 2-term compensation (Yh*Hh + Yh*Hl).
#define ATTN_STAGE 69120
#define ATTN_SMEM  (2112 + 2 * ATTN_STAGE)
__global__ __launch_bounds__(256)
void attnmma_k(const __nv_bfloat16* __restrict__ Yh,
               const __nv_bfloat16* __restrict__ Hh, const __nv_bfloat16* __restrict__ Hl,
               const float* __restrict__ Yn, const float* __restrict__ Hn,
               const unsigned char* __restrict__ mask, float* __restrict__ Out)
{
    constexpr int NSTEP = ADIM / 32;   // 12
    extern __shared__ char smem[];
    float* sHnM = (float*)smem;
    float* sRed = (float*)(smem + 1600);
    const unsigned int su = sm_u32(smem);

    const int tid  = threadIdx.x;
    const int lane = tid & 31;
    const int wid  = tid >> 5;
    const int wm   = wid & 3;
    const int wn   = wid >> 2;
    const int b    = blockIdx.y;
    const int m0   = blockIdx.x * 64;

    for (int i = tid; i < 400; i += 256)
        sHnM[i] = mask[b * TTEXT + i] ? __int_as_float(0x7f800000) : Hn[b * TTEXT + i];

    auto fill = [&](int step) {
        int s = step & 1;
        int kc = step * 32;
        unsigned int st = su + 2112 + s * ATTN_STAGE;
        #pragma unroll 2
        for (int i = tid; i < 1600; i += 256) {
            int n = i >> 2, q = i & 3;
            unsigned int dst = st + 5120 + (n * 20 + q * 4) * 4;
            size_t src = ((size_t)b * TTEXT + n) * ADIM + kc + q * 8;
            cp16(dst,         Hh + src, 16u);
            cp16(dst + 32000, Hl + src, 16u);
        }
        {
            int i = tid;
            int r = i >> 2, q = i & 3;
            unsigned int dst = st + (r * 20 + q * 4) * 4;
            size_t src = ((size_t)b * TMEL + m0 + r) * ADIM + kc + q * 8;
            cp16(dst, Yh + src, 16u);
        }
        cp_commit();
    };

    float acc[25][4];
    #pragma unroll
    for (int j = 0; j < 25; j++)
        #pragma unroll
        for (int e = 0; e < 4; e++) acc[j][e] = 0.f;

    const int r0 = lane >> 2;
    const int lw = lane & 3;

    fill(0);
    for (int step = 0; step < NSTEP; step++) {
        int s = step & 1;
        if (step + 1 < NSTEP) { fill(step + 1); cp_wait<1>(); }
        else                  { cp_wait<0>(); }
        __syncthreads();

        const unsigned int st = su + 2112 + s * ATTN_STAGE;
        const uint32_t* Ys_h = (const uint32_t*)(smem + (st - su));
        const uint32_t* Hs_h = Ys_h + 1280;
        const uint32_t* Hs_l = Hs_h + 8000;

        #pragma unroll
        for (int kq = 0; kq < 2; kq++) {
            const int w0 = kq * 8 + lw;
            unsigned int ah[4];
            {
                int ra = (wm * 16 + r0) * 20;
                int rb = (wm * 16 + r0 + 8) * 20;
                ah[0] = Ys_h[ra + w0];     ah[1] = Ys_h[rb + w0];
                ah[2] = Ys_h[ra + w0 + 4]; ah[3] = Ys_h[rb + w0 + 4];
            }
            #pragma unroll
            for (int j = 0; j < 25; j++) {
                int n = (wn * 200 + j * 8 + r0) * 20;
                unsigned int bh[2], bl[2];
                bh[0] = Hs_h[n + w0]; bh[1] = Hs_h[n + w0 + 4];
                bl[0] = Hs_l[n + w0]; bl[1] = Hs_l[n + w0 + 4];
                mma16816(acc[j], ah, bh);
                mma16816(acc[j], ah, bl);
            }
        }
        __syncthreads();
    }

    int mrow0 = m0 + wm * 16 + r0;
    float yn0 = Yn[b * TMEL + mrow0];
    float yn1 = Yn[b * TMEL + mrow0 + 8];

    #pragma unroll
    for (int j = 0; j < 25; j++) {
        int c = wn * 200 + j * 8 + lw * 2;
        float hn0 = sHnM[c], hn1 = sHnM[c + 1];
        acc[j][0] = -sqrtf(fmaxf(yn0 + hn0 - 2.f * acc[j][0], 1e-12f));
        acc[j][1] = -sqrtf(fmaxf(yn0 + hn1 - 2.f * acc[j][1], 1e-12f));
        acc[j][2] = -sqrtf(fmaxf(yn1 + hn0 - 2.f * acc[j][2], 1e-12f));
        acc[j][3] = -sqrtf(fmaxf(yn1 + hn1 - 2.f * acc[j][3], 1e-12f));
    }

    float mx0 = -INFINITY, mx1 = -INFINITY;
    #pragma unroll
    for (int j = 0; j < 25; j++) {
        mx0 = fmaxf(mx0, fmaxf(acc[j][0], acc[j][1]));
        mx1 = fmaxf(mx1, fmaxf(acc[j][2], acc[j][3]));
    }
    #pragma unroll
    for (int o = 1; o <= 2; o <<= 1) {
        mx0 = fmaxf(mx0, __shfl_xor_sync(0xffffffffu, mx0, o));
        mx1 = fmaxf(mx1, __shfl_xor_sync(0xffffffffu, mx1, o));
    }
    if (lw == 0) {
        sRed[(wm * 16 + r0) * 2 + wn]     = mx0;
        sRed[(wm * 16 + r0 + 8) * 2 + wn] = mx1;
    }
    __syncthreads();
    mx0 = fmaxf(sRed[(wm * 16 + r0) * 2],     sRed[(wm * 16 + r0) * 2 + 1]);
    mx1 = fmaxf(sRed[(wm * 16 + r0 + 8) * 2], sRed[(wm * 16 + r0 + 8) * 2 + 1]);
    __syncthreads();

    float sm0 = 0.f, sm1 = 0.f;
    #pragma unroll
    for (int j = 0; j < 25; j++) {
        sm0 += __expf(acc[j][0] - mx0) + __expf(acc[j][1] - mx0);
        sm1 += __expf(acc[j][2] - mx1) + __expf(acc[j][3] - mx1);
    }
    #pragma unroll
    for (int o = 1; o <= 2; o <<= 1) {
        sm0 += __shfl_xor_sync(0xffffffffu, sm0, o);
        sm1 += __shfl_xor_sync(0xffffffffu, sm1, o);
    }
    if (lw == 0) {
        sRed[(wm * 16 + r0) * 2 + wn]     = sm0;
        sRed[(wm * 16 + r0 + 8) * 2 + wn] = sm1;
    }
    __syncthreads();
    sm0 = sRed[(wm * 16 + r0) * 2]     + sRed[(wm * 16 + r0) * 2 + 1];
    sm1 = sRed[(wm * 16 + r0 + 8) * 2] + sRed[(wm * 16 + r0 + 8) * 2 + 1];
    float lse0 = mx0 + __logf(sm0);
    float lse1 = mx1 + __logf(sm1);

    float* o0 = Out + ((size_t)b * TMEL + mrow0) * TTEXT;
    float* o1 = Out + ((size_t)b * TMEL + mrow0 + 8) * TTEXT;
    #pragma unroll
    for (int j = 0; j < 25; j++) {
        int c = wn * 200 + j * 8 + lw * 2;
        *(float2*)&o0[c] = make_float2(acc[j][0] - lse0, acc[j][1] - lse0);
        *(float2*)&o1[c] = make_float2(acc[j][2] - lse1, acc[j][3] - lse1);
    }
}

// ---------------- launch ----------------
extern "C" void kernel_launch(void* const* d_in, const int* in_sizes, int n_in,
                              void* d_out, int out_size)
{
    const float* hs   = (const float*)d_in[0];
    const float* ys   = (const float*)d_in[1];
    const unsigned char* mask = (const unsigned char*)d_in[2];
    const float* t_w1 = (const float*)d_in[3];
    const float* t_b1 = (const float*)d_in[4];
    const float* t_w2 = (const float*)d_in[5];
    const float* t_b2 = (const float*)d_in[6];
    const float* m_w1 = (const float*)d_in[7];
    const float* m_b1 = (const float*)d_in[8];
    const float* m_w2 = (const float*)d_in[9];
    const float* m_b2 = (const float*)d_in[10];
    const float* m_w3 = (const float*)d_in[11];
    const float* m_b3 = (const float*)d_in[12];
    float* out = (float*)d_out;

    __nv_bfloat16 *xht, *xlt, *xin, *h1h, *xhm, *y1h, *y2h;
    __nv_bfloat16 *wt1h, *wt1l, *wt2h, *wt2l, *wm1h, *wm1l, *wm2h, *wm2l, *wm3h, *wm3l;
    float *hn, *yn;
    cudaGetSymbolAddress((void**)&xht, g_xht); cudaGetSymbolAddress((void**)&xlt, g_xlt);
    cudaGetSymbolAddress((void**)&xin, g_xin); cudaGetSymbolAddress((void**)&h1h, g_h1h);
    cudaGetSymbolAddress((void**)&xhm, g_xhm);
    cudaGetSymbolAddress((void**)&y1h, g_y1h); cudaGetSymbolAddress((void**)&y2h, g_y2h);
    cudaGetSymbolAddress((void**)&wt1h, g_wt1h); cudaGetSymbolAddress((void**)&wt1l, g_wt1l);
    cudaGetSymbolAddress((void**)&wt2h, g_wt2h); cudaGetSymbolAddress((void**)&wt2l, g_wt2l);
    cudaGetSymbolAddress((void**)&wm1h, g_wm1h); cudaGetSymbolAddress((void**)&wm1l, g_wm1l);
    cudaGetSymbolAddress((void**)&wm2h, g_wm2h); cudaGetSymbolAddress((void**)&wm2l, g_wm2l);
    cudaGetSymbolAddress((void**)&wm3h, g_wm3h); cudaGetSymbolAddress((void**)&wm3l, g_wm3l);
    cudaGetSymbolAddress((void**)&hn, g_hn);   cudaGetSymbolAddress((void**)&yn, g_yn);

    cudaFuncSetAttribute(convmma_k<3, 384, true,  false>,
                         cudaFuncAttributeMaxDynamicSharedMemorySize, CONV_SMEM);
    cudaFuncSetAttribute(convmma_k<1, 384, false, true >,
                         cudaFuncAttributeMaxDynamicSharedMemorySize, CONV_SMEM);
    cudaFuncSetAttribute(convmma_k<1, 384, false, false>,
                         cudaFuncAttributeMaxDynamicSharedMemorySize, CONV_SMEM);
    cudaFuncSetAttribute(convmma_k<3, 128, true,  false>,
                         cudaFuncAttributeMaxDynamicSharedMemorySize, CONV_SMEM);
    cudaFuncSetAttribute(attnmma_k,
                         cudaFuncAttributeMaxDynamicSharedMemorySize, ATTN_SMEM);

    // #0: merged input split (hi only)
    {
        long mel = (long)BB * TMEL * CIPM;
        dim3 g((unsigned)((mel + 255) / 256), 2);
        xsplit_all_k<<<g, 256>>>(hs, ys, xin, xhm);
    }
    // #1: merged weight split
    {
        dim3 g((3 * 384 * ADIM + 255) / 256, 5);
        wsplit_all_k<<<g, 256>>>(t_w1, t_w2, m_w1, m_w2, m_w3,
                                 wt1h, wt1l, wt2h, wt2l, wm1h, wm1l,
                                 wm2h, wm2l, wm3h, wm3l);
    }

    // #2-#3: text prenet (conv2 output feeds attn B side -> hi+lo)
    {
        dim3 g((TTEXT + 63) / 64, 3, BB);
        convmma_k<3, 384, true,  false><<<g, 256, CONV_SMEM>>>(
            xin, wt1h, wt1l, t_b1, h1h, nullptr, TTEXT);
        convmma_k<1, 384, false, true ><<<g, 256, CONV_SMEM>>>(
            h1h, wt2h, wt2l, t_b2, xht, xlt, TTEXT);
    }
    // #4-#6: mel prenet (#5 = mel conv2, the ncu-profiled launch)
    {
        dim3 g((TMEL + 63) / 64, 3, BB);
        convmma_k<3, 128, true,  false><<<g, 256, CONV_SMEM>>>(
            xhm, wm1h, wm1l, m_b1, y1h, nullptr, TMEL);
        convmma_k<3, 384, true,  false><<<g, 256, CONV_SMEM>>>(
            y1h, wm2h, wm2l, m_b2, y2h, nullptr, TMEL);
        convmma_k<1, 384, false, false><<<g, 256, CONV_SMEM>>>(
            y2h, wm3h, wm3l, m_b3, y1h, nullptr, TMEL);
    }

    // row norms: Y from hi only (matches dot operand), H from hi+lo
    rownorm2_k<<<BB * TTEXT, 128>>>(xht, xlt, hn);
    rownorm2_k<<<BB * TMEL, 128>>>(y1h, nullptr, yn);

    // fused distance + log_softmax (tensor-core, 2-term)
    {
        dim3 g(TMEL / 64, BB);
        attnmma_k<<<g, 256, ATTN_SMEM>>>(y1h, xht, xlt, yn, hn, mask, out);
    }
}